// round 5
// baseline (speedup 1.0000x reference)
#include <cuda_runtime.h>
#include <cuda_bf16.h>
#include <cstdint>
#include <math.h>

#define B_   2
#define S_   2048
#define D_   4096
#define H_   32
#define HK_  8
#define HD_  128
#define M_   (B_ * S_)          // 4096 total tokens
#define KVD_ (HK_ * HD_)        // 1024
#define DP_  (D_ / 2)           // 2048 u32 pairs per row (K=4096)

// ---------------- scratch (device globals; no allocation allowed) ----------------
__device__ float    g_q[(size_t)M_ * D_];
__device__ float    g_k[(size_t)M_ * KVD_];
__device__ float    g_v[(size_t)M_ * KVD_];
// split planes (bf16 pairs packed in u32): [rows][K/2]
__device__ unsigned g_xh[(size_t)M_ * DP_],   g_xl[(size_t)M_ * DP_];
__device__ unsigned g_wqh[(size_t)D_ * DP_],  g_wql[(size_t)D_ * DP_];
__device__ unsigned g_wkh[(size_t)KVD_ * DP_],g_wkl[(size_t)KVD_ * DP_];
__device__ unsigned g_wvh[(size_t)KVD_ * DP_],g_wvl[(size_t)KVD_ * DP_];
__device__ unsigned g_woh[(size_t)D_ * DP_],  g_wol[(size_t)D_ * DP_];
__device__ unsigned g_ah[(size_t)M_ * DP_],   g_al[(size_t)M_ * DP_];  // attention out

// ---------------- helpers ----------------
__device__ __forceinline__ void split2(float x, float y, unsigned& hi, unsigned& lo) {
    __nv_bfloat16 xh = __float2bfloat16_rn(x);
    __nv_bfloat16 yh = __float2bfloat16_rn(y);
    __nv_bfloat16 xl = __float2bfloat16_rn(x - __bfloat162float(xh));
    __nv_bfloat16 yl = __float2bfloat16_rn(y - __bfloat162float(yh));
    hi = (unsigned)__bfloat16_as_ushort(xh) | ((unsigned)__bfloat16_as_ushort(yh) << 16);
    lo = (unsigned)__bfloat16_as_ushort(xl) | ((unsigned)__bfloat16_as_ushort(yl) << 16);
}

__device__ __forceinline__ void mma_bf16(float* c, const unsigned* a, unsigned b0, unsigned b1) {
    asm volatile(
        "mma.sync.aligned.m16n8k16.row.col.f32.bf16.bf16.f32 "
        "{%0,%1,%2,%3}, {%4,%5,%6,%7}, {%8,%9}, {%0,%1,%2,%3};\n"
        : "+f"(c[0]), "+f"(c[1]), "+f"(c[2]), "+f"(c[3])
        : "r"(a[0]), "r"(a[1]), "r"(a[2]), "r"(a[3]), "r"(b0), "r"(b1));
}

__device__ __forceinline__ void mma3(float* c, const unsigned* ah, const unsigned* al,
                                     unsigned b0h, unsigned b1h, unsigned b0l, unsigned b1l) {
    mma_bf16(c, ah, b0h, b1h);
    mma_bf16(c, ah, b0l, b1l);
    mma_bf16(c, al, b0h, b1h);
}

__device__ __forceinline__ void cpa16(unsigned saddr, const void* g) {
    asm volatile("cp.async.cg.shared.global [%0], [%1], 16;" :: "r"(saddr), "l"(g));
}

__device__ __forceinline__ uint32_t s2u(const void* p) {
    uint32_t a;
    asm("{ .reg .u64 t; cvta.to.shared.u64 t, %1; cvt.u32.u64 %0, t; }" : "=r"(a) : "l"(p));
    return a;
}

__device__ __forceinline__ void ldsm4(unsigned* r, uint32_t a) {
    asm volatile("ldmatrix.sync.aligned.m8n8.x4.shared.b16 {%0,%1,%2,%3}, [%4];"
                 : "=r"(r[0]), "=r"(r[1]), "=r"(r[2]), "=r"(r[3]) : "r"(a));
}

// ---------------- split pass: fp32 -> bf16 hi/lo planes ----------------
__global__ void split_kernel(const float* __restrict__ X,
                             unsigned* __restrict__ Hh, unsigned* __restrict__ Ll,
                             int npairs)
{
    int i = blockIdx.x * blockDim.x + threadIdx.x;
    if (i >= npairs) return;
    float2 v = ((const float2*)X)[i];
    split2(v.x, v.y, Hh[i], Ll[i]);
}

// =====================================================================
// bf16x3 GEMM via ldmatrix + mma.sync:
// C[M,N] = A[M,K] * B[N,K]^T (hi/lo split planes).
// CTA tile 128x256, K-chunk 32, 2-stage cp.async.
// 8 warps (2x4), warp tile 64x64: per k16 -> 16 LDSM.x4 + 96 HMMA.
// =====================================================================
#define RSTR 80                       // smem bytes per row (64B data + 16B pad)
#define APL (128 * RSTR)              // 10240 B per A plane
#define BPL (256 * RSTR)              // 20480 B per B plane
#define STG (2 * APL + 2 * BPL)       // 61440 B per stage
#define G_SMEM (2 * STG)              // 122880 B

__global__ void __launch_bounds__(256, 1)
gemm3(const unsigned* __restrict__ Ah, const unsigned* __restrict__ Al,
      const unsigned* __restrict__ Bh, const unsigned* __restrict__ Bl,
      float* __restrict__ C, int N, int K)
{
    extern __shared__ char ds[];
    const uint32_t sbase = s2u(ds);

    const int tid  = threadIdx.x;
    const int lane = tid & 31;
    const int warp = tid >> 5;
    const int m0 = blockIdx.y * 128;
    const int n0 = blockIdx.x * 256;
    const int wm = (warp >> 2) * 64;
    const int wn = (warp & 3) * 64;
    const int KP = K >> 1;                      // u32 per row

    // ---- cp.async geometry ----
    // A: thread t -> row t>>1, 32B half (t&1), both planes (2+2 cp.async)
    // B: thread t -> row t (full 64B), both planes (4+4 cp.async)
    const unsigned* gah = Ah + (size_t)(m0 + (tid >> 1)) * KP + (tid & 1) * 8;
    const unsigned* gal = Al + (size_t)(m0 + (tid >> 1)) * KP + (tid & 1) * 8;
    const unsigned* gbh = Bh + (size_t)(n0 + tid) * KP;
    const unsigned* gbl = Bl + (size_t)(n0 + tid) * KP;
    const unsigned aoffA = (unsigned)((tid >> 1) * RSTR + (tid & 1) * 32);
    const unsigned boffB = (unsigned)(tid * RSTR);

    // ---- ldmatrix fragment addresses (offsets within a plane) ----
    unsigned aoff[4], boff[4];
#pragma unroll
    for (int mi = 0; mi < 4; mi++)
        aoff[mi] = (unsigned)((wm + mi * 16 + (lane & 15)) * RSTR + ((lane >> 4) << 4));
#pragma unroll
    for (int j = 0; j < 4; j++)
        boff[j] = (unsigned)((wn + j * 16 + (lane & 7) + ((lane >> 4) << 3)) * RSTR
                             + (((lane >> 3) & 1) << 4));

    float acc[4][8][4];
#pragma unroll
    for (int i = 0; i < 4; i++)
#pragma unroll
        for (int j = 0; j < 8; j++)
#pragma unroll
            for (int c = 0; c < 4; c++) acc[i][j][c] = 0.0f;

    const int nch = K / 32;

    auto issue = [&](int c, int stg) {
        const unsigned sb = sbase + (unsigned)stg * STG;
        const int go = c * 16;                  // u32 per row per chunk
        cpa16(sb + aoffA,            gah + go);
        cpa16(sb + aoffA + 16,       gah + go + 4);
        cpa16(sb + APL + aoffA,      gal + go);
        cpa16(sb + APL + aoffA + 16, gal + go + 4);
#pragma unroll
        for (int s = 0; s < 4; s++) {
            cpa16(sb + 2 * APL + boffB + s * 16,       gbh + go + s * 4);
            cpa16(sb + 2 * APL + BPL + boffB + s * 16, gbl + go + s * 4);
        }
        asm volatile("cp.async.commit_group;");
    };

    issue(0, 0);

    for (int c = 0; c < nch; c++) {
        if (c + 1 < nch) {
            issue(c + 1, (c + 1) & 1);
            asm volatile("cp.async.wait_group 1;");
        } else {
            asm volatile("cp.async.wait_group 0;");
        }
        __syncthreads();

        const unsigned sb = sbase + (unsigned)(c & 1) * STG;
        const unsigned sAh = sb, sAl = sb + APL;
        const unsigned sBh = sb + 2 * APL, sBl = sBh + BPL;

#pragma unroll
        for (int kk = 0; kk < 2; kk++) {
            unsigned afh[4][4], afl[4][4], bfh[4][4], bfl[4][4];
#pragma unroll
            for (int mi = 0; mi < 4; mi++) {
                ldsm4(afh[mi], sAh + aoff[mi] + kk * 32);
                ldsm4(afl[mi], sAl + aoff[mi] + kk * 32);
            }
#pragma unroll
            for (int j = 0; j < 4; j++) {
                ldsm4(bfh[j], sBh + boff[j] + kk * 32);
                ldsm4(bfl[j], sBl + boff[j] + kk * 32);
            }
#pragma unroll
            for (int mi = 0; mi < 4; mi++) {
#pragma unroll
                for (int j = 0; j < 4; j++) {
                    mma3(acc[mi][2 * j],     afh[mi], afl[mi],
                         bfh[j][0], bfh[j][1], bfl[j][0], bfl[j][1]);
                    mma3(acc[mi][2 * j + 1], afh[mi], afl[mi],
                         bfh[j][2], bfh[j][3], bfl[j][2], bfl[j][3]);
                }
            }
        }
        __syncthreads();
    }

    // ---- epilogue ----
    const int grp = lane >> 2;
    const int qid = lane & 3;
#pragma unroll
    for (int mi = 0; mi < 4; mi++) {
        int row = m0 + wm + mi * 16 + grp;
#pragma unroll
        for (int nj = 0; nj < 8; nj++) {
            int col = n0 + wn + nj * 8 + qid * 2;
            *(float2*)(C + (size_t)row * N + col)       = make_float2(acc[mi][nj][0], acc[mi][nj][1]);
            *(float2*)(C + (size_t)(row + 8) * N + col) = make_float2(acc[mi][nj][2], acc[mi][nj][3]);
        }
    }
}

// =====================================================================
// RoPE (interleaved pairs). X: [M_, heads*128]. lh = log2(heads).
// =====================================================================
__global__ void rope_kernel(float* __restrict__ X,
                            const float* __restrict__ cs,
                            const float* __restrict__ sn,
                            int lh, int total)
{
    int idx = blockIdx.x * blockDim.x + threadIdx.x;
    if (idx >= total) return;
    int d2   = idx & 63;
    int rest = idx >> 6;
    int row  = rest >> lh;
    int s    = row & (S_ - 1);
    float c  = cs[s * 64 + d2];
    float sv = sn[s * 64 + d2];
    float2* p = ((float2*)X) + idx;
    float2 v = *p;
    *p = make_float2(v.x * c - v.y * sv, v.x * sv + v.y * c);
}

// =====================================================================
// Flash attention, bf16x3 tensor cores (mma.sync), causal, GQA.
// BM=128 q rows per CTA, BN=64 kv per tile, HD=128. 256 threads = 8 warps.
// =====================================================================
#define KSTR 68    // K smem stride (64 pairs + 4)
#define VSTR 36    // Vt/P smem stride (32 pairs + 4)

__global__ void __launch_bounds__(256) attn_mma(const float* __restrict__ Q,
                                                const float* __restrict__ K,
                                                const float* __restrict__ V,
                                                unsigned* __restrict__ Oh,
                                                unsigned* __restrict__ Ol)
{
    extern __shared__ unsigned smu[];
    unsigned* Kh  = smu;                    // [64][KSTR]
    unsigned* Kl  = Kh  + 64 * KSTR;
    unsigned* Vth = Kl  + 64 * KSTR;        // [128][VSTR]  (d-major, kv pairs)
    unsigned* Vtl = Vth + 128 * VSTR;
    unsigned* Ph  = Vtl + 128 * VSTR;       // [128][VSTR]
    unsigned* Pl  = Ph  + 128 * VSTR;

    const int tid  = threadIdx.x;
    const int lane = tid & 31;
    const int warp = tid >> 5;
    const int grp  = lane >> 2;
    const int qid  = lane & 3;
    const int qt = blockIdx.x;
    const int h  = blockIdx.y;
    const int b  = blockIdx.z;
    const int hk = h >> 2;
    const int q0  = qt * 128;
    const int wq0 = warp * 16;

    unsigned qh[8][4], ql[8][4];
    {
        const float scale = 0.08838834764831845f;
        const float* qb = Q + (size_t)(b * S_ + q0 + wq0) * D_ + h * HD_;
#pragma unroll
        for (int kk = 0; kk < 8; kk++) {
            float2 v;
            v = *(const float2*)(qb + (size_t)grp * D_ + kk * 16 + 2 * qid);
            split2(v.x * scale, v.y * scale, qh[kk][0], ql[kk][0]);
            v = *(const float2*)(qb + (size_t)(grp + 8) * D_ + kk * 16 + 2 * qid);
            split2(v.x * scale, v.y * scale, qh[kk][1], ql[kk][1]);
            v = *(const float2*)(qb + (size_t)grp * D_ + kk * 16 + 2 * qid + 8);
            split2(v.x * scale, v.y * scale, qh[kk][2], ql[kk][2]);
            v = *(const float2*)(qb + (size_t)(grp + 8) * D_ + kk * 16 + 2 * qid + 8);
            split2(v.x * scale, v.y * scale, qh[kk][3], ql[kk][3]);
        }
    }

    float o_acc[16][4];
#pragma unroll
    for (int i = 0; i < 16; i++)
#pragma unroll
        for (int c = 0; c < 4; c++) o_acc[i][c] = 0.0f;
    float m0r = -1e30f, m1r = -1e30f, l0r = 0.0f, l1r = 0.0f;

    const float* kbase = K + (size_t)(b * S_) * KVD_ + hk * HD_;
    const float* vbase = V + (size_t)(b * S_) * KVD_ + hk * HD_;
    const int qrow0 = q0 + wq0 + grp;
    const int tmax = 2 * qt + 1;

    const int lr = tid >> 2;
    const int ld0 = (tid & 3) * 32;

    for (int t = 0; t <= tmax; t++) {
        const int kv0 = t * 64;
        __syncthreads();
        {
            const float* kp = kbase + (size_t)(kv0 + lr) * KVD_ + ld0;
            unsigned* khr = Kh + lr * KSTR + ld0 / 2;
            unsigned* klr = Kl + lr * KSTR + ld0 / 2;
#pragma unroll
            for (int i = 0; i < 8; i++) {
                float4 v = *(const float4*)(kp + i * 4);
                split2(v.x, v.y, khr[i * 2],     klr[i * 2]);
                split2(v.z, v.w, khr[i * 2 + 1], klr[i * 2 + 1]);
            }
            const float* vp = vbase + (size_t)(kv0 + lr) * KVD_ + ld0;
            __nv_bfloat16* vh16 = (__nv_bfloat16*)Vth;
            __nv_bfloat16* vl16 = (__nv_bfloat16*)Vtl;
            const int half = lr & 1, rp = lr >> 1;
#pragma unroll
            for (int i = 0; i < 8; i++) {
                float4 v = *(const float4*)(vp + i * 4);
                float vv[4] = {v.x, v.y, v.z, v.w};
#pragma unroll
                for (int j = 0; j < 4; j++) {
                    int d = ld0 + i * 4 + j;
                    __nv_bfloat16 hb = __float2bfloat16_rn(vv[j]);
                    __nv_bfloat16 lb = __float2bfloat16_rn(vv[j] - __bfloat162float(hb));
                    vh16[(d * VSTR + rp) * 2 + half] = hb;
                    vl16[(d * VSTR + rp) * 2 + half] = lb;
                }
            }
        }
        __syncthreads();

        if (kv0 > q0 + wq0 + 15) continue;

        float s[8][4];
#pragma unroll
        for (int nj = 0; nj < 8; nj++)
#pragma unroll
            for (int c = 0; c < 4; c++) s[nj][c] = 0.0f;

#pragma unroll
        for (int kk = 0; kk < 8; kk++) {
#pragma unroll
            for (int nj = 0; nj < 8; nj++) {
                const unsigned* ph = Kh + (nj * 8 + grp) * KSTR + kk * 8 + qid;
                const unsigned* pl = Kl + (nj * 8 + grp) * KSTR + kk * 8 + qid;
                mma3(s[nj], qh[kk], ql[kk], ph[0], ph[4], pl[0], pl[4]);
            }
        }

        if (kv0 + 63 > q0 + wq0) {
#pragma unroll
            for (int nj = 0; nj < 8; nj++) {
                int kcol = kv0 + nj * 8 + 2 * qid;
                if (kcol     > qrow0)     s[nj][0] = -1e30f;
                if (kcol + 1 > qrow0)     s[nj][1] = -1e30f;
                if (kcol     > qrow0 + 8) s[nj][2] = -1e30f;
                if (kcol + 1 > qrow0 + 8) s[nj][3] = -1e30f;
            }
        }

        float rm0 = -1e30f, rm1 = -1e30f;
#pragma unroll
        for (int nj = 0; nj < 8; nj++) {
            rm0 = fmaxf(rm0, fmaxf(s[nj][0], s[nj][1]));
            rm1 = fmaxf(rm1, fmaxf(s[nj][2], s[nj][3]));
        }
        rm0 = fmaxf(rm0, __shfl_xor_sync(0xffffffffu, rm0, 1));
        rm0 = fmaxf(rm0, __shfl_xor_sync(0xffffffffu, rm0, 2));
        rm1 = fmaxf(rm1, __shfl_xor_sync(0xffffffffu, rm1, 1));
        rm1 = fmaxf(rm1, __shfl_xor_sync(0xffffffffu, rm1, 2));

        float mn0 = fmaxf(m0r, rm0), mn1 = fmaxf(m1r, rm1);
        float a0 = __expf(m0r - mn0), a1 = __expf(m1r - mn1);
        m0r = mn0; m1r = mn1;

        float rs0 = 0.0f, rs1 = 0.0f;
#pragma unroll
        for (int nj = 0; nj < 8; nj++) {
            s[nj][0] = __expf(s[nj][0] - mn0);
            s[nj][1] = __expf(s[nj][1] - mn0);
            s[nj][2] = __expf(s[nj][2] - mn1);
            s[nj][3] = __expf(s[nj][3] - mn1);
            rs0 += s[nj][0] + s[nj][1];
            rs1 += s[nj][2] + s[nj][3];
        }
        rs0 += __shfl_xor_sync(0xffffffffu, rs0, 1);
        rs0 += __shfl_xor_sync(0xffffffffu, rs0, 2);
        rs1 += __shfl_xor_sync(0xffffffffu, rs1, 1);
        rs1 += __shfl_xor_sync(0xffffffffu, rs1, 2);
        l0r = l0r * a0 + rs0;
        l1r = l1r * a1 + rs1;

#pragma unroll
        for (int nj = 0; nj < 16; nj++) {
            o_acc[nj][0] *= a0; o_acc[nj][1] *= a0;
            o_acc[nj][2] *= a1; o_acc[nj][3] *= a1;
        }

#pragma unroll
        for (int nj = 0; nj < 8; nj++) {
            unsigned hi, lo;
            split2(s[nj][0], s[nj][1], hi, lo);
            Ph[(wq0 + grp) * VSTR + nj * 4 + qid] = hi;
            Pl[(wq0 + grp) * VSTR + nj * 4 + qid] = lo;
            split2(s[nj][2], s[nj][3], hi, lo);
            Ph[(wq0 + grp + 8) * VSTR + nj * 4 + qid] = hi;
            Pl[(wq0 + grp + 8) * VSTR + nj * 4 + qid] = lo;
        }
        __syncwarp();

#pragma unroll
        for (int kk = 0; kk < 4; kk++) {
            unsigned ah[4], al[4];
            const unsigned* p0 = Ph + (wq0 + grp) * VSTR + kk * 8 + qid;
            const unsigned* p1 = Ph + (wq0 + grp + 8) * VSTR + kk * 8 + qid;
            ah[0] = p0[0]; ah[1] = p1[0]; ah[2] = p0[4]; ah[3] = p1[4];
            const unsigned* q0p = Pl + (wq0 + grp) * VSTR + kk * 8 + qid;
            const unsigned* q1p = Pl + (wq0 + grp + 8) * VSTR + kk * 8 + qid;
            al[0] = q0p[0]; al[1] = q1p[0]; al[2] = q0p[4]; al[3] = q1p[4];
#pragma unroll
            for (int nj = 0; nj < 16; nj++) {
                const unsigned* bh = Vth + (nj * 8 + grp) * VSTR + kk * 8 + qid;
                const unsigned* bl = Vtl + (nj * 8 + grp) * VSTR + kk * 8 + qid;
                mma3(o_acc[nj], ah, al, bh[0], bh[4], bl[0], bl[4]);
            }
        }
    }

    const float il0 = 1.0f / l0r;
    const float il1 = 1.0f / l1r;
    const size_t r0 = (size_t)(b * S_ + q0 + wq0 + grp) * DP_;
    const size_t r1 = (size_t)(b * S_ + q0 + wq0 + grp + 8) * DP_;
#pragma unroll
    for (int nj = 0; nj < 16; nj++) {
        int col = h * 64 + nj * 4 + qid;
        unsigned hi, lo;
        split2(o_acc[nj][0] * il0, o_acc[nj][1] * il0, hi, lo);
        Oh[r0 + col] = hi; Ol[r0 + col] = lo;
        split2(o_acc[nj][2] * il1, o_acc[nj][3] * il1, hi, lo);
        Oh[r1 + col] = hi; Ol[r1 + col] = lo;
    }
}

// =====================================================================
// launch
// =====================================================================
extern "C" void kernel_launch(void* const* d_in, const int* in_sizes, int n_in,
                              void* d_out, int out_size)
{
    const float* x  = (const float*)d_in[0];
    const float* fc = (const float*)d_in[1];
    const float* fs = (const float*)d_in[2];
    const float* wq = (const float*)d_in[3];
    const float* wk = (const float*)d_in[4];
    const float* wv = (const float*)d_in[5];
    const float* wo = (const float*)d_in[6];
    float* out = (float*)d_out;

    float *q, *k, *v;
    unsigned *xh, *xl, *wqh, *wql, *wkh, *wkl, *wvh, *wvl, *woh, *wol, *ah, *al;
    cudaGetSymbolAddress((void**)&q,   g_q);
    cudaGetSymbolAddress((void**)&k,   g_k);
    cudaGetSymbolAddress((void**)&v,   g_v);
    cudaGetSymbolAddress((void**)&xh,  g_xh);  cudaGetSymbolAddress((void**)&xl,  g_xl);
    cudaGetSymbolAddress((void**)&wqh, g_wqh); cudaGetSymbolAddress((void**)&wql, g_wql);
    cudaGetSymbolAddress((void**)&wkh, g_wkh); cudaGetSymbolAddress((void**)&wkl, g_wkl);
    cudaGetSymbolAddress((void**)&wvh, g_wvh); cudaGetSymbolAddress((void**)&wvl, g_wvl);
    cudaGetSymbolAddress((void**)&woh, g_woh); cudaGetSymbolAddress((void**)&wol, g_wol);
    cudaGetSymbolAddress((void**)&ah,  g_ah);  cudaGetSymbolAddress((void**)&al,  g_al);

    // splits
    {
        int np;
        np = M_ * DP_;   split_kernel<<<np / 256, 256>>>(x,  xh,  xl,  np);
        np = D_ * DP_;   split_kernel<<<np / 256, 256>>>(wq, wqh, wql, np);
        np = KVD_ * DP_; split_kernel<<<np / 256, 256>>>(wk, wkh, wkl, np);
        np = KVD_ * DP_; split_kernel<<<np / 256, 256>>>(wv, wvh, wvl, np);
        np = D_ * DP_;   split_kernel<<<np / 256, 256>>>(wo, woh, wol, np);
    }

    cudaFuncSetAttribute(gemm3, cudaFuncAttributeMaxDynamicSharedMemorySize, G_SMEM);

    // QKV projections (ldmatrix + mma.sync bf16x3)
    gemm3<<<dim3(16, 32), 256, G_SMEM>>>(xh, xl, wqh, wql, q, D_,   D_);
    gemm3<<<dim3(4,  32), 256, G_SMEM>>>(xh, xl, wkh, wkl, k, KVD_, D_);
    gemm3<<<dim3(4,  32), 256, G_SMEM>>>(xh, xl, wvh, wvl, v, KVD_, D_);

    // RoPE
    {
        int tq = M_ * H_ * 64;
        rope_kernel<<<(tq + 255) / 256, 256>>>(q, fc, fs, 5, tq);
        int tk = M_ * HK_ * 64;
        rope_kernel<<<(tk + 255) / 256, 256>>>(k, fc, fs, 3, tk);
    }

    // attention
    {
        const int ASMEM = (2 * 64 * KSTR + 4 * 128 * VSTR) * 4;   // 108544 B
        cudaFuncSetAttribute(attn_mma, cudaFuncAttributeMaxDynamicSharedMemorySize, ASMEM);
        attn_mma<<<dim3(S_ / 128, H_, B_), 256, ASMEM>>>(q, k, v, ah, al);
    }

    // output projection
    gemm3<<<dim3(16, 32), 256, G_SMEM>>>(ah, al, woh, wol, out, D_, D_);
}

// round 6
// speedup vs baseline: 1.1350x; 1.1350x over previous
#include <cuda_runtime.h>
#include <cuda_bf16.h>
#include <cstdint>
#include <math.h>

#define B_   2
#define S_   2048
#define D_   4096
#define H_   32
#define HK_  8
#define HD_  128
#define M_   (B_ * S_)          // 4096 total tokens
#define KVD_ (HK_ * HD_)        // 1024
#define DP_  (D_ / 2)           // 2048 u32 pairs per row (K=4096)
#define SP_  (S_ / 2)           // 1024 seq pairs

// ---------------- scratch (device globals; no allocation allowed) ----------------
__device__ float    g_q[(size_t)M_ * D_];
__device__ float    g_k[(size_t)M_ * KVD_];
__device__ float    g_v[(size_t)M_ * KVD_];
// split planes (bf16 pairs packed in u32)
__device__ unsigned g_xh[(size_t)M_ * DP_],   g_xl[(size_t)M_ * DP_];
__device__ unsigned g_wqh[(size_t)D_ * DP_],  g_wql[(size_t)D_ * DP_];
__device__ unsigned g_wkh[(size_t)KVD_ * DP_],g_wkl[(size_t)KVD_ * DP_];
__device__ unsigned g_wvh[(size_t)KVD_ * DP_],g_wvl[(size_t)KVD_ * DP_];
__device__ unsigned g_woh[(size_t)D_ * DP_],  g_wol[(size_t)D_ * DP_];
__device__ unsigned g_ah[(size_t)M_ * DP_],   g_al[(size_t)M_ * DP_];   // attention out
// attention operand planes
__device__ unsigned g_qh[(size_t)M_ * DP_],   g_ql[(size_t)M_ * DP_];   // roped+scaled Q
__device__ unsigned g_khp[(size_t)B_ * HK_ * S_ * 64], g_klp[(size_t)B_ * HK_ * S_ * 64]; // [b,hk,s,64 d-pairs]
__device__ unsigned g_vth[(size_t)B_ * HK_ * HD_ * SP_], g_vtl[(size_t)B_ * HK_ * HD_ * SP_]; // [b,hk,d,s-pairs]

// ---------------- helpers ----------------
__device__ __forceinline__ void split2(float x, float y, unsigned& hi, unsigned& lo) {
    __nv_bfloat16 xh = __float2bfloat16_rn(x);
    __nv_bfloat16 yh = __float2bfloat16_rn(y);
    __nv_bfloat16 xl = __float2bfloat16_rn(x - __bfloat162float(xh));
    __nv_bfloat16 yl = __float2bfloat16_rn(y - __bfloat162float(yh));
    hi = (unsigned)__bfloat16_as_ushort(xh) | ((unsigned)__bfloat16_as_ushort(yh) << 16);
    lo = (unsigned)__bfloat16_as_ushort(xl) | ((unsigned)__bfloat16_as_ushort(yl) << 16);
}

__device__ __forceinline__ void mma_bf16(float* c, const unsigned* a, unsigned b0, unsigned b1) {
    asm volatile(
        "mma.sync.aligned.m16n8k16.row.col.f32.bf16.bf16.f32 "
        "{%0,%1,%2,%3}, {%4,%5,%6,%7}, {%8,%9}, {%0,%1,%2,%3};\n"
        : "+f"(c[0]), "+f"(c[1]), "+f"(c[2]), "+f"(c[3])
        : "r"(a[0]), "r"(a[1]), "r"(a[2]), "r"(a[3]), "r"(b0), "r"(b1));
}

__device__ __forceinline__ void mma3(float* c, const unsigned* ah, const unsigned* al,
                                     unsigned b0h, unsigned b1h, unsigned b0l, unsigned b1l) {
    mma_bf16(c, ah, b0h, b1h);
    mma_bf16(c, ah, b0l, b1l);
    mma_bf16(c, al, b0h, b1h);
}

__device__ __forceinline__ void cpa16(unsigned saddr, const void* g) {
    asm volatile("cp.async.cg.shared.global [%0], [%1], 16;" :: "r"(saddr), "l"(g));
}

__device__ __forceinline__ uint32_t s2u(const void* p) {
    uint32_t a;
    asm("{ .reg .u64 t; cvta.to.shared.u64 t, %1; cvt.u32.u64 %0, t; }" : "=r"(a) : "l"(p));
    return a;
}

// ---------------- split pass: fp32 -> bf16 hi/lo planes ----------------
__global__ void split_kernel(const float* __restrict__ X,
                             unsigned* __restrict__ Hh, unsigned* __restrict__ Ll,
                             int npairs)
{
    int i = blockIdx.x * blockDim.x + threadIdx.x;
    if (i >= npairs) return;
    float2 v = ((const float2*)X)[i];
    split2(v.x, v.y, Hh[i], Ll[i]);
}

// ---------------- RoPE + scale + split Q -> planes [row][DP_] ----------------
__global__ void rope_split_q(const float* __restrict__ Q,
                             const float* __restrict__ cs, const float* __restrict__ sn,
                             unsigned* __restrict__ Oh, unsigned* __restrict__ Ol)
{
    int idx = blockIdx.x * blockDim.x + threadIdx.x;   // over M_*H_*64 pairs
    int d2   = idx & 63;
    int rest = idx >> 6;
    int h    = rest & 31;
    int row  = rest >> 5;
    int s    = row & (S_ - 1);
    float c  = cs[s * 64 + d2];
    float sv = sn[s * 64 + d2];
    float2 v = ((const float2*)Q)[idx];
    const float scale = 0.08838834764831845f;
    float o0 = (v.x * c - v.y * sv) * scale;
    float o1 = (v.x * sv + v.y * c) * scale;
    unsigned hi, lo;
    split2(o0, o1, hi, lo);
    size_t o = (size_t)row * DP_ + h * 64 + d2;
    Oh[o] = hi; Ol[o] = lo;
}

// ---------------- RoPE + split K -> planes [b,hk,s,64 pairs] ----------------
__global__ void rope_split_k(const float* __restrict__ K,
                             const float* __restrict__ cs, const float* __restrict__ sn,
                             unsigned* __restrict__ Oh, unsigned* __restrict__ Ol)
{
    int idx = blockIdx.x * blockDim.x + threadIdx.x;   // over M_*HK_*64 pairs
    int d2   = idx & 63;
    int rest = idx >> 6;
    int h    = rest & 7;
    int row  = rest >> 3;
    int s    = row & (S_ - 1);
    int b    = row >> 11;
    float c  = cs[s * 64 + d2];
    float sv = sn[s * 64 + d2];
    float2 v = ((const float2*)K)[idx];
    float o0 = v.x * c - v.y * sv;
    float o1 = v.x * sv + v.y * c;
    unsigned hi, lo;
    split2(o0, o1, hi, lo);
    size_t o = ((size_t)(b * HK_ + h) * S_ + s) * 64 + d2;
    Oh[o] = hi; Ol[o] = lo;
}

// ---------------- transpose + split V -> planes [b,hk,d,s-pairs] ----------------
__global__ void __launch_bounds__(256) transpose_split_v(const float* __restrict__ V,
                                                         unsigned* __restrict__ Oh,
                                                         unsigned* __restrict__ Ol)
{
    __shared__ float sm[64 * 132];
    const int tid = threadIdx.x;
    const int s0  = blockIdx.x * 64;
    const int hk  = blockIdx.y;
    const int b   = blockIdx.z;

    // load 64 s-rows x 128 d (coalesced)
#pragma unroll
    for (int i = 0; i < 32; i++) {
        int idx = tid + i * 256;
        int r = idx >> 7, c = idx & 127;
        sm[r * 132 + c] = V[(size_t)(b * S_ + s0 + r) * KVD_ + hk * HD_ + c];
    }
    __syncthreads();

    // write: thread -> d = tid>>1, 16 consecutive s-pairs
    const int d  = tid >> 1;
    const int pb = (tid & 1) * 16;
    unsigned* oh = Oh + ((size_t)(b * HK_ + hk) * HD_ + d) * SP_ + (s0 >> 1) + pb;
    unsigned* ol = Ol + ((size_t)(b * HK_ + hk) * HD_ + d) * SP_ + (s0 >> 1) + pb;
#pragma unroll
    for (int i = 0; i < 16; i++) {
        int p = pb + i;
        float f0 = sm[(2 * p) * 132 + d];
        float f1 = sm[(2 * p + 1) * 132 + d];
        unsigned hi, lo;
        split2(f0, f1, hi, lo);
        oh[i] = hi; ol[i] = lo;
    }
}

// =====================================================================
// bf16x3 GEMM (round-3 structure, 3-stage cp.async):
// C[M,N] = A[M,K]*B[N,K]^T, 128x128 tile, BK=32, 8 warps of 64x32.
// =====================================================================
#define GSTR 20                  // smem row stride in u32 (16 pairs + pad)
#define GPL  (128 * GSTR)        // u32 per plane
#define GSTGU (4 * GPL)          // u32 per stage (4 planes) = 10240
#define G_SMEM (3 * GSTGU * 4)   // 122880 B

__global__ void __launch_bounds__(256, 1)
gemm3(const unsigned* __restrict__ Ah, const unsigned* __restrict__ Al,
      const unsigned* __restrict__ Bh, const unsigned* __restrict__ Bl,
      float* __restrict__ C, int N, int K)
{
    extern __shared__ unsigned gs[];

    const int tid  = threadIdx.x;
    const int lane = tid & 31;
    const int warp = tid >> 5;
    const int m0 = blockIdx.y << 7;
    const int n0 = blockIdx.x << 7;
    const int wm = (warp >> 2) * 64;
    const int wn = (warp & 3) * 32;
    const int grp = lane >> 2;
    const int qid = lane & 3;
    const int KP = K >> 1;

    const int lr = tid >> 1;
    const int lc = (tid & 1) * 8;
    const unsigned* agh = Ah + (size_t)(m0 + lr) * KP + lc;
    const unsigned* agl = Al + (size_t)(m0 + lr) * KP + lc;
    const unsigned* bgh = Bh + (size_t)(n0 + lr) * KP + lc;
    const unsigned* bgl = Bl + (size_t)(n0 + lr) * KP + lc;

    const unsigned sbase = s2u(gs);
    const unsigned srow = (lr * GSTR + lc) * 4;   // byte offset within plane

    float acc[4][4][4];
#pragma unroll
    for (int i = 0; i < 4; i++)
#pragma unroll
        for (int j = 0; j < 4; j++)
#pragma unroll
            for (int c = 0; c < 4; c++) acc[i][j][c] = 0.0f;

    const int nch = K / 32;

    auto issue = [&](int c, int stg) {
        unsigned st = sbase + (unsigned)(stg * GSTGU * 4) + srow;
        const int go = c * 16;
        cpa16(st,                 agh + go);     cpa16(st + 16,                 agh + go + 4);
        cpa16(st + GPL * 4,       agl + go);     cpa16(st + GPL * 4 + 16,       agl + go + 4);
        cpa16(st + 2 * GPL * 4,   bgh + go);     cpa16(st + 2 * GPL * 4 + 16,   bgh + go + 4);
        cpa16(st + 3 * GPL * 4,   bgl + go);     cpa16(st + 3 * GPL * 4 + 16,   bgl + go + 4);
        asm volatile("cp.async.commit_group;");
    };

    issue(0, 0);
    if (nch > 1) issue(1, 1);

    int stg = 0;
    for (int c = 0; c < nch; c++) {
        if (c + 2 < nch) issue(c + 2, (stg + 2) % 3);
        const int rem = nch - 1 - c;
        if (rem >= 2)      { asm volatile("cp.async.wait_group 2;"); }
        else if (rem == 1) { asm volatile("cp.async.wait_group 1;"); }
        else               { asm volatile("cp.async.wait_group 0;"); }
        __syncthreads();

        const unsigned* Ash = gs + stg * GSTGU;
        const unsigned* Asl = Ash + GPL;
        const unsigned* Bsh = Ash + 2 * GPL;
        const unsigned* Bsl = Ash + 3 * GPL;

#pragma unroll
        for (int kk = 0; kk < 2; kk++) {
            unsigned ah[4][4], al[4][4], bh[4][2], bl[4][2];
#pragma unroll
            for (int mi = 0; mi < 4; mi++) {
                const unsigned* p = Ash + (wm + mi * 16 + grp) * GSTR + kk * 8 + qid;
                ah[mi][0] = p[0]; ah[mi][1] = p[8 * GSTR];
                ah[mi][2] = p[4]; ah[mi][3] = p[8 * GSTR + 4];
                const unsigned* q = Asl + (wm + mi * 16 + grp) * GSTR + kk * 8 + qid;
                al[mi][0] = q[0]; al[mi][1] = q[8 * GSTR];
                al[mi][2] = q[4]; al[mi][3] = q[8 * GSTR + 4];
            }
#pragma unroll
            for (int nj = 0; nj < 4; nj++) {
                const unsigned* p = Bsh + (wn + nj * 8 + grp) * GSTR + kk * 8 + qid;
                bh[nj][0] = p[0]; bh[nj][1] = p[4];
                const unsigned* q = Bsl + (wn + nj * 8 + grp) * GSTR + kk * 8 + qid;
                bl[nj][0] = q[0]; bl[nj][1] = q[4];
            }
#pragma unroll
            for (int mi = 0; mi < 4; mi++)
#pragma unroll
                for (int nj = 0; nj < 4; nj++)
                    mma3(acc[mi][nj], ah[mi], al[mi],
                         bh[nj][0], bh[nj][1], bl[nj][0], bl[nj][1]);
        }
        __syncthreads();
        stg = (stg + 1) % 3;
    }

#pragma unroll
    for (int mi = 0; mi < 4; mi++) {
        int row0 = m0 + wm + mi * 16 + grp;
#pragma unroll
        for (int nj = 0; nj < 4; nj++) {
            int col = n0 + wn + nj * 8 + qid * 2;
            *(float2*)(C + (size_t)row0 * N + col)       = make_float2(acc[mi][nj][0], acc[mi][nj][1]);
            *(float2*)(C + (size_t)(row0 + 8) * N + col) = make_float2(acc[mi][nj][2], acc[mi][nj][3]);
        }
    }
}

// =====================================================================
// Flash attention, bf16x3 mma.sync, causal, GQA.
// Pre-split operands; cp.async 2-stage K/V tile pipeline.
// BM=128 q rows per CTA, BN=64 kv per tile. 256 threads = 8 warps.
// =====================================================================
#define KSTR 68                          // K tile row stride (u32): 64 pairs + 4
#define VSTR 36                          // Vt/P row stride (u32): 32 pairs + 4
#define KPLU (64 * KSTR)                 // 4352 u32 per K plane
#define VPLU (128 * VSTR)                // 4608 u32 per Vt plane
#define ASTGU (2 * KPLU + 2 * VPLU)      // 17920 u32 per stage
#define A_SMEM ((2 * ASTGU + 2 * VPLU) * 4)   // stages + P planes = 180224 B

__global__ void __launch_bounds__(256, 1) attn_mma(const unsigned* __restrict__ Qh,
                                                   const unsigned* __restrict__ Ql,
                                                   const unsigned* __restrict__ Kp,
                                                   const unsigned* __restrict__ Klp,
                                                   const unsigned* __restrict__ Vth,
                                                   const unsigned* __restrict__ Vtl,
                                                   unsigned* __restrict__ Oh,
                                                   unsigned* __restrict__ Ol)
{
    extern __shared__ unsigned smu[];
    const unsigned sm_base = s2u(smu);
    unsigned* Ph = smu + 2 * ASTGU;
    unsigned* Pl = Ph + VPLU;

    const int tid  = threadIdx.x;
    const int lane = tid & 31;
    const int warp = tid >> 5;
    const int grp  = lane >> 2;
    const int qid  = lane & 3;
    const int qt = blockIdx.x;
    const int h  = blockIdx.y;
    const int b  = blockIdx.z;
    const int hk = h >> 2;
    const int q0  = qt * 128;
    const int wq0 = warp * 16;

    const unsigned* kbh = Kp  + (size_t)(b * HK_ + hk) * S_ * 64;
    const unsigned* kbl = Klp + (size_t)(b * HK_ + hk) * S_ * 64;
    const unsigned* vbh = Vth + (size_t)(b * HK_ + hk) * HD_ * SP_;
    const unsigned* vbl = Vtl + (size_t)(b * HK_ + hk) * HD_ * SP_;

    // ---- Q fragments from planes ----
    unsigned qh[8][4], ql[8][4];
    {
        const unsigned* q0h = Qh + (size_t)(b * S_ + q0 + wq0) * DP_ + h * 64;
        const unsigned* q0l = Ql + (size_t)(b * S_ + q0 + wq0) * DP_ + h * 64;
#pragma unroll
        for (int kk = 0; kk < 8; kk++) {
            qh[kk][0] = q0h[(size_t)grp * DP_ + kk * 8 + qid];
            qh[kk][1] = q0h[(size_t)(grp + 8) * DP_ + kk * 8 + qid];
            qh[kk][2] = q0h[(size_t)grp * DP_ + kk * 8 + qid + 4];
            qh[kk][3] = q0h[(size_t)(grp + 8) * DP_ + kk * 8 + qid + 4];
            ql[kk][0] = q0l[(size_t)grp * DP_ + kk * 8 + qid];
            ql[kk][1] = q0l[(size_t)(grp + 8) * DP_ + kk * 8 + qid];
            ql[kk][2] = q0l[(size_t)grp * DP_ + kk * 8 + qid + 4];
            ql[kk][3] = q0l[(size_t)(grp + 8) * DP_ + kk * 8 + qid + 4];
        }
    }

    float o_acc[16][4];
#pragma unroll
    for (int i = 0; i < 16; i++)
#pragma unroll
        for (int c = 0; c < 4; c++) o_acc[i][c] = 0.0f;
    float m0r = -1e30f, m1r = -1e30f, l0r = 0.0f, l1r = 0.0f;

    const int qrow0 = q0 + wq0 + grp;
    const int tmax = 2 * qt + 1;

    // cp.async geometry
    const int krr = tid >> 2;            // K row 0..63
    const int kcc = tid & 3;             // chunk base
    const int vrr = tid >> 1;            // Vt row (d) 0..127
    const int vcc = tid & 1;

    auto issueT = [&](int tt, int stg) {
        const unsigned sb = sm_base + (unsigned)(stg * ASTGU * 4);
        const int kv = tt * 64;
        const unsigned* gkh = kbh + (size_t)(kv + krr) * 64 + kcc * 4;
        const unsigned* gkl = kbl + (size_t)(kv + krr) * 64 + kcc * 4;
        const unsigned ks = sb + krr * (KSTR * 4) + kcc * 16;
#pragma unroll
        for (int j = 0; j < 4; j++) {
            cpa16(ks + j * 64,                gkh + j * 16);
            cpa16(ks + KPLU * 4 + j * 64,     gkl + j * 16);
        }
        const unsigned* gvh = vbh + (size_t)vrr * SP_ + (kv >> 1) + vcc * 4;
        const unsigned* gvl = vbl + (size_t)vrr * SP_ + (kv >> 1) + vcc * 4;
        const unsigned vs = sb + 2 * KPLU * 4 + vrr * (VSTR * 4) + vcc * 16;
#pragma unroll
        for (int j = 0; j < 4; j++) {
            cpa16(vs + j * 32,                gvh + j * 8);
            cpa16(vs + VPLU * 4 + j * 32,     gvl + j * 8);
        }
        asm volatile("cp.async.commit_group;");
    };

    issueT(0, 0);

    for (int t = 0; t <= tmax; t++) {
        const int kv0 = t * 64;
        if (t < tmax) {
            issueT(t + 1, (t + 1) & 1);
            asm volatile("cp.async.wait_group 1;");
        } else {
            asm volatile("cp.async.wait_group 0;");
        }
        __syncthreads();

        if (kv0 <= q0 + wq0 + 15) {
            const unsigned* sKh = smu + (t & 1) * ASTGU;
            const unsigned* sKl = sKh + KPLU;
            const unsigned* sVh = sKl + KPLU;
            const unsigned* sVl = sVh + VPLU;

            // ---- S = Q K^T ----
            float s[8][4];
#pragma unroll
            for (int nj = 0; nj < 8; nj++)
#pragma unroll
                for (int c = 0; c < 4; c++) s[nj][c] = 0.0f;

#pragma unroll
            for (int kk = 0; kk < 8; kk++) {
#pragma unroll
                for (int nj = 0; nj < 8; nj++) {
                    const unsigned* ph = sKh + (nj * 8 + grp) * KSTR + kk * 8 + qid;
                    const unsigned* pl = sKl + (nj * 8 + grp) * KSTR + kk * 8 + qid;
                    mma3(s[nj], qh[kk], ql[kk], ph[0], ph[4], pl[0], pl[4]);
                }
            }

            if (kv0 + 63 > q0 + wq0) {
#pragma unroll
                for (int nj = 0; nj < 8; nj++) {
                    int kcol = kv0 + nj * 8 + 2 * qid;
                    if (kcol     > qrow0)     s[nj][0] = -1e30f;
                    if (kcol + 1 > qrow0)     s[nj][1] = -1e30f;
                    if (kcol     > qrow0 + 8) s[nj][2] = -1e30f;
                    if (kcol + 1 > qrow0 + 8) s[nj][3] = -1e30f;
                }
            }

            // ---- online softmax ----
            float rm0 = -1e30f, rm1 = -1e30f;
#pragma unroll
            for (int nj = 0; nj < 8; nj++) {
                rm0 = fmaxf(rm0, fmaxf(s[nj][0], s[nj][1]));
                rm1 = fmaxf(rm1, fmaxf(s[nj][2], s[nj][3]));
            }
            rm0 = fmaxf(rm0, __shfl_xor_sync(0xffffffffu, rm0, 1));
            rm0 = fmaxf(rm0, __shfl_xor_sync(0xffffffffu, rm0, 2));
            rm1 = fmaxf(rm1, __shfl_xor_sync(0xffffffffu, rm1, 1));
            rm1 = fmaxf(rm1, __shfl_xor_sync(0xffffffffu, rm1, 2));

            float mn0 = fmaxf(m0r, rm0), mn1 = fmaxf(m1r, rm1);
            float a0 = __expf(m0r - mn0), a1 = __expf(m1r - mn1);
            m0r = mn0; m1r = mn1;

            float rs0 = 0.0f, rs1 = 0.0f;
#pragma unroll
            for (int nj = 0; nj < 8; nj++) {
                s[nj][0] = __expf(s[nj][0] - mn0);
                s[nj][1] = __expf(s[nj][1] - mn0);
                s[nj][2] = __expf(s[nj][2] - mn1);
                s[nj][3] = __expf(s[nj][3] - mn1);
                rs0 += s[nj][0] + s[nj][1];
                rs1 += s[nj][2] + s[nj][3];
            }
            rs0 += __shfl_xor_sync(0xffffffffu, rs0, 1);
            rs0 += __shfl_xor_sync(0xffffffffu, rs0, 2);
            rs1 += __shfl_xor_sync(0xffffffffu, rs1, 1);
            rs1 += __shfl_xor_sync(0xffffffffu, rs1, 2);
            l0r = l0r * a0 + rs0;
            l1r = l1r * a1 + rs1;

#pragma unroll
            for (int nj = 0; nj < 16; nj++) {
                o_acc[nj][0] *= a0; o_acc[nj][1] *= a0;
                o_acc[nj][2] *= a1; o_acc[nj][3] *= a1;
            }

            // ---- write P (exact hi/lo split), warp-private rows ----
#pragma unroll
            for (int nj = 0; nj < 8; nj++) {
                unsigned hi, lo;
                split2(s[nj][0], s[nj][1], hi, lo);
                Ph[(wq0 + grp) * VSTR + nj * 4 + qid] = hi;
                Pl[(wq0 + grp) * VSTR + nj * 4 + qid] = lo;
                split2(s[nj][2], s[nj][3], hi, lo);
                Ph[(wq0 + grp + 8) * VSTR + nj * 4 + qid] = hi;
                Pl[(wq0 + grp + 8) * VSTR + nj * 4 + qid] = lo;
            }
            __syncwarp();

            // ---- O += P V ----
#pragma unroll
            for (int kk = 0; kk < 4; kk++) {
                unsigned ah[4], al[4];
                const unsigned* p0 = Ph + (wq0 + grp) * VSTR + kk * 8 + qid;
                const unsigned* p1 = Ph + (wq0 + grp + 8) * VSTR + kk * 8 + qid;
                ah[0] = p0[0]; ah[1] = p1[0]; ah[2] = p0[4]; ah[3] = p1[4];
                const unsigned* q0p = Pl + (wq0 + grp) * VSTR + kk * 8 + qid;
                const unsigned* q1p = Pl + (wq0 + grp + 8) * VSTR + kk * 8 + qid;
                al[0] = q0p[0]; al[1] = q1p[0]; al[2] = q0p[4]; al[3] = q1p[4];
#pragma unroll
                for (int nj = 0; nj < 16; nj++) {
                    const unsigned* bh = sVh + (nj * 8 + grp) * VSTR + kk * 8 + qid;
                    const unsigned* bl = sVl + (nj * 8 + grp) * VSTR + kk * 8 + qid;
                    mma3(o_acc[nj], ah, al, bh[0], bh[4], bl[0], bl[4]);
                }
            }
        }
        __syncthreads();
    }

    // ---- epilogue: normalize + split-store ----
    const float il0 = 1.0f / l0r;
    const float il1 = 1.0f / l1r;
    const size_t r0 = (size_t)(b * S_ + q0 + wq0 + grp) * DP_;
    const size_t r1 = (size_t)(b * S_ + q0 + wq0 + grp + 8) * DP_;
#pragma unroll
    for (int nj = 0; nj < 16; nj++) {
        int col = h * 64 + nj * 4 + qid;
        unsigned hi, lo;
        split2(o_acc[nj][0] * il0, o_acc[nj][1] * il0, hi, lo);
        Oh[r0 + col] = hi; Ol[r0 + col] = lo;
        split2(o_acc[nj][2] * il1, o_acc[nj][3] * il1, hi, lo);
        Oh[r1 + col] = hi; Ol[r1 + col] = lo;
    }
}

// =====================================================================
// launch
// =====================================================================
extern "C" void kernel_launch(void* const* d_in, const int* in_sizes, int n_in,
                              void* d_out, int out_size)
{
    const float* x  = (const float*)d_in[0];
    const float* fc = (const float*)d_in[1];
    const float* fs = (const float*)d_in[2];
    const float* wq = (const float*)d_in[3];
    const float* wk = (const float*)d_in[4];
    const float* wv = (const float*)d_in[5];
    const float* wo = (const float*)d_in[6];
    float* out = (float*)d_out;

    float *q, *k, *v;
    unsigned *xh, *xl, *wqh, *wql, *wkh, *wkl, *wvh, *wvl, *woh, *wol, *ah, *al;
    unsigned *qh, *ql, *khp, *klp, *vth, *vtl;
    cudaGetSymbolAddress((void**)&q,   g_q);
    cudaGetSymbolAddress((void**)&k,   g_k);
    cudaGetSymbolAddress((void**)&v,   g_v);
    cudaGetSymbolAddress((void**)&xh,  g_xh);  cudaGetSymbolAddress((void**)&xl,  g_xl);
    cudaGetSymbolAddress((void**)&wqh, g_wqh); cudaGetSymbolAddress((void**)&wql, g_wql);
    cudaGetSymbolAddress((void**)&wkh, g_wkh); cudaGetSymbolAddress((void**)&wkl, g_wkl);
    cudaGetSymbolAddress((void**)&wvh, g_wvh); cudaGetSymbolAddress((void**)&wvl, g_wvl);
    cudaGetSymbolAddress((void**)&woh, g_woh); cudaGetSymbolAddress((void**)&wol, g_wol);
    cudaGetSymbolAddress((void**)&ah,  g_ah);  cudaGetSymbolAddress((void**)&al,  g_al);
    cudaGetSymbolAddress((void**)&qh,  g_qh);  cudaGetSymbolAddress((void**)&ql,  g_ql);
    cudaGetSymbolAddress((void**)&khp, g_khp); cudaGetSymbolAddress((void**)&klp, g_klp);
    cudaGetSymbolAddress((void**)&vth, g_vth); cudaGetSymbolAddress((void**)&vtl, g_vtl);

    // input splits
    {
        int np;
        np = M_ * DP_;   split_kernel<<<np / 256, 256>>>(x,  xh,  xl,  np);
        np = D_ * DP_;   split_kernel<<<np / 256, 256>>>(wq, wqh, wql, np);
        np = KVD_ * DP_; split_kernel<<<np / 256, 256>>>(wk, wkh, wkl, np);
        np = KVD_ * DP_; split_kernel<<<np / 256, 256>>>(wv, wvh, wvl, np);
        np = D_ * DP_;   split_kernel<<<np / 256, 256>>>(wo, woh, wol, np);
    }

    cudaFuncSetAttribute(gemm3, cudaFuncAttributeMaxDynamicSharedMemorySize, G_SMEM);

    // QKV projections
    gemm3<<<dim3(32, 32), 256, G_SMEM>>>(xh, xl, wqh, wql, q, D_,   D_);
    gemm3<<<dim3(8,  32), 256, G_SMEM>>>(xh, xl, wkh, wkl, k, KVD_, D_);
    gemm3<<<dim3(8,  32), 256, G_SMEM>>>(xh, xl, wvh, wvl, v, KVD_, D_);

    // RoPE + split + (V) transpose preprocessing
    rope_split_q<<<(M_ * H_ * 64) / 256, 256>>>(q, fc, fs, qh, ql);
    rope_split_k<<<(M_ * HK_ * 64) / 256, 256>>>(k, fc, fs, khp, klp);
    transpose_split_v<<<dim3(S_ / 64, HK_, B_), 256>>>(v, vth, vtl);

    // attention
    cudaFuncSetAttribute(attn_mma, cudaFuncAttributeMaxDynamicSharedMemorySize, A_SMEM);
    attn_mma<<<dim3(S_ / 128, H_, B_), 256, A_SMEM>>>(qh, ql, khp, klp, vth, vtl, ah, al);

    // output projection
    gemm3<<<dim3(32, 32), 256, G_SMEM>>>(ah, al, woh, wol, out, D_, D_);
}

// round 7
// speedup vs baseline: 1.1689x; 1.0299x over previous
#include <cuda_runtime.h>
#include <cuda_bf16.h>
#include <cstdint>
#include <math.h>

#define B_   2
#define S_   2048
#define D_   4096
#define H_   32
#define HK_  8
#define HD_  128
#define M_   (B_ * S_)          // 4096 total tokens
#define KVD_ (HK_ * HD_)        // 1024
#define DP_  (D_ / 2)           // 2048 u32 pairs per row
#define SP_  (S_ / 2)           // 1024 seq pairs

// ---------------- scratch (device globals; no allocation allowed) ----------------
__device__ float    g_v[(size_t)M_ * KVD_];
// split planes (bf16 pairs packed in u32)
__device__ unsigned g_xh[(size_t)M_ * DP_],   g_xl[(size_t)M_ * DP_];
__device__ unsigned g_wqh[(size_t)D_ * DP_],  g_wql[(size_t)D_ * DP_];
__device__ unsigned g_wkh[(size_t)KVD_ * DP_],g_wkl[(size_t)KVD_ * DP_];
__device__ unsigned g_wvh[(size_t)KVD_ * DP_],g_wvl[(size_t)KVD_ * DP_];
__device__ unsigned g_woh[(size_t)D_ * DP_],  g_wol[(size_t)D_ * DP_];
__device__ unsigned g_ah[(size_t)M_ * DP_],   g_al[(size_t)M_ * DP_];   // attention out
// attention operand planes
__device__ unsigned g_qh[(size_t)M_ * DP_],   g_ql[(size_t)M_ * DP_];   // roped+scaled Q
__device__ unsigned g_khp[(size_t)B_ * HK_ * S_ * 64], g_klp[(size_t)B_ * HK_ * S_ * 64]; // [b,hk,s,64]
__device__ unsigned g_vth[(size_t)B_ * HK_ * HD_ * SP_], g_vtl[(size_t)B_ * HK_ * HD_ * SP_]; // [b,hk,d,sp]

// ---------------- helpers ----------------
__device__ __forceinline__ void split2(float x, float y, unsigned& hi, unsigned& lo) {
    __nv_bfloat16 xh = __float2bfloat16_rn(x);
    __nv_bfloat16 yh = __float2bfloat16_rn(y);
    __nv_bfloat16 xl = __float2bfloat16_rn(x - __bfloat162float(xh));
    __nv_bfloat16 yl = __float2bfloat16_rn(y - __bfloat162float(yh));
    hi = (unsigned)__bfloat16_as_ushort(xh) | ((unsigned)__bfloat16_as_ushort(yh) << 16);
    lo = (unsigned)__bfloat16_as_ushort(xl) | ((unsigned)__bfloat16_as_ushort(yl) << 16);
}

__device__ __forceinline__ void mma_bf16(float* c, const unsigned* a, unsigned b0, unsigned b1) {
    asm volatile(
        "mma.sync.aligned.m16n8k16.row.col.f32.bf16.bf16.f32 "
        "{%0,%1,%2,%3}, {%4,%5,%6,%7}, {%8,%9}, {%0,%1,%2,%3};\n"
        : "+f"(c[0]), "+f"(c[1]), "+f"(c[2]), "+f"(c[3])
        : "r"(a[0]), "r"(a[1]), "r"(a[2]), "r"(a[3]), "r"(b0), "r"(b1));
}

__device__ __forceinline__ void mma3(float* c, const unsigned* ah, const unsigned* al,
                                     unsigned b0h, unsigned b1h, unsigned b0l, unsigned b1l) {
    mma_bf16(c, ah, b0h, b1h);
    mma_bf16(c, ah, b0l, b1l);
    mma_bf16(c, al, b0h, b1h);
}

__device__ __forceinline__ void cpa16(unsigned saddr, const void* g) {
    asm volatile("cp.async.cg.shared.global [%0], [%1], 16;" :: "r"(saddr), "l"(g));
}

__device__ __forceinline__ uint32_t s2u(const void* p) {
    uint32_t a;
    asm("{ .reg .u64 t; cvta.to.shared.u64 t, %1; cvt.u32.u64 %0, t; }" : "=r"(a) : "l"(p));
    return a;
}

// ---------------- split pass: fp32 -> bf16 hi/lo planes ----------------
__global__ void split_kernel(const float* __restrict__ X,
                             unsigned* __restrict__ Hh, unsigned* __restrict__ Ll,
                             int npairs)
{
    int i = blockIdx.x * blockDim.x + threadIdx.x;
    if (i >= npairs) return;
    float2 v = ((const float2*)X)[i];
    split2(v.x, v.y, Hh[i], Ll[i]);
}

// ---------------- transpose + split V -> planes [b,hk,d,s-pairs] ----------------
__global__ void __launch_bounds__(256) transpose_split_v(const float* __restrict__ V,
                                                         unsigned* __restrict__ Oh,
                                                         unsigned* __restrict__ Ol)
{
    __shared__ float sm[64 * 132];
    const int tid = threadIdx.x;
    const int s0  = blockIdx.x * 64;
    const int hk  = blockIdx.y;
    const int b   = blockIdx.z;

#pragma unroll
    for (int i = 0; i < 32; i++) {
        int idx = tid + i * 256;
        int r = idx >> 7, c = idx & 127;
        sm[r * 132 + c] = V[(size_t)(b * S_ + s0 + r) * KVD_ + hk * HD_ + c];
    }
    __syncthreads();

    const int d  = tid >> 1;
    const int pb = (tid & 1) * 16;
    unsigned* oh = Oh + ((size_t)(b * HK_ + hk) * HD_ + d) * SP_ + (s0 >> 1) + pb;
    unsigned* ol = Ol + ((size_t)(b * HK_ + hk) * HD_ + d) * SP_ + (s0 >> 1) + pb;
#pragma unroll
    for (int i = 0; i < 16; i++) {
        int p = pb + i;
        float f0 = sm[(2 * p) * 132 + d];
        float f1 = sm[(2 * p + 1) * 132 + d];
        unsigned hi, lo;
        split2(f0, f1, hi, lo);
        oh[i] = hi; ol[i] = lo;
    }
}

// =====================================================================
// bf16x3 GEMM: C[M,N] = A[M,K]*B[N,K]^T  (hi/lo split planes)
// CTA tile 256x128, BK=32 (16 pairs), 512 threads = 16 warps (4x4 grid
// of 64x32 warp tiles), 3-stage cp.async.
// MODE 0: fp32 C.  MODE 1: rope+scale+split -> Q planes [row][DP_].
// MODE 2: rope+split -> K planes [b,hk,s,64].
// =====================================================================
#define GSTR 20                    // smem row stride (u32): 16 data + 4 pad
#define APLU (256 * GSTR)          // A plane u32 (5120)
#define BPLU (128 * GSTR)          // B plane u32 (2560)
#define GSTGU (2 * APLU + 2 * BPLU)   // stage u32 = 15360
#define G_SMEM (3 * GSTGU * 4)        // 184320 B

template <int MODE>
__global__ void __launch_bounds__(512, 1)
gemm3(const unsigned* __restrict__ Ah, const unsigned* __restrict__ Al,
      const unsigned* __restrict__ Bh, const unsigned* __restrict__ Bl,
      float* __restrict__ C, unsigned* __restrict__ Oh, unsigned* __restrict__ Ol,
      const float* __restrict__ cs, const float* __restrict__ sn,
      int N, int K)
{
    extern __shared__ unsigned gs[];

    const int tid  = threadIdx.x;
    const int lane = tid & 31;
    const int warp = tid >> 5;
    const int m0 = blockIdx.y << 8;            // 256-row tile
    const int n0 = blockIdx.x << 7;            // 128-col tile
    const int wm = (warp >> 2) * 64;
    const int wn = (warp & 3) * 32;
    const int grp = lane >> 2;
    const int qid = lane & 3;
    const int KP = K >> 1;

    // cp.async mapping
    const int lra = tid >> 1;                  // A row 0..255
    const int lca = (tid & 1) * 8;             // u32 offset 0/8
    const int lrb = tid >> 2;                  // B row 0..127
    const int lcb = (tid & 3) * 4;             // u32 offset 0..12
    const unsigned* agh = Ah + (size_t)(m0 + lra) * KP + lca;
    const unsigned* agl = Al + (size_t)(m0 + lra) * KP + lca;
    const unsigned* bgh = Bh + (size_t)(n0 + lrb) * KP + lcb;
    const unsigned* bgl = Bl + (size_t)(n0 + lrb) * KP + lcb;

    const unsigned sbase = s2u(gs);
    const unsigned sra = (lra * GSTR + lca) * 4;
    const unsigned srb = (lrb * GSTR + lcb) * 4;

    float acc[4][4][4];
#pragma unroll
    for (int i = 0; i < 4; i++)
#pragma unroll
        for (int j = 0; j < 4; j++)
#pragma unroll
            for (int c = 0; c < 4; c++) acc[i][j][c] = 0.0f;

    const int nch = K / 32;

    auto issue = [&](int c, int stg) {
        unsigned sb = sbase + (unsigned)(stg * GSTGU * 4);
        const int go = c * 16;
        cpa16(sb + sra,                     agh + go);
        cpa16(sb + sra + 16,                agh + go + 4);
        cpa16(sb + APLU * 4 + sra,          agl + go);
        cpa16(sb + APLU * 4 + sra + 16,     agl + go + 4);
        cpa16(sb + 2 * APLU * 4 + srb,          bgh + go);
        cpa16(sb + (2 * APLU + BPLU) * 4 + srb, bgl + go);
        asm volatile("cp.async.commit_group;");
    };

    issue(0, 0);
    if (nch > 1) issue(1, 1);

    int stg = 0;
    for (int c = 0; c < nch; c++) {
        if (c + 2 < nch) issue(c + 2, (stg + 2) % 3);
        const int rem = nch - 1 - c;
        if (rem >= 2)      { asm volatile("cp.async.wait_group 2;"); }
        else if (rem == 1) { asm volatile("cp.async.wait_group 1;"); }
        else               { asm volatile("cp.async.wait_group 0;"); }
        __syncthreads();

        const unsigned* Ash = gs + stg * GSTGU;
        const unsigned* Asl = Ash + APLU;
        const unsigned* Bsh = Ash + 2 * APLU;
        const unsigned* Bsl = Ash + 2 * APLU + BPLU;

#pragma unroll
        for (int kk = 0; kk < 2; kk++) {
            unsigned ah[4][4], al[4][4], bh[4][2], bl[4][2];
#pragma unroll
            for (int mi = 0; mi < 4; mi++) {
                const unsigned* p = Ash + (wm + mi * 16 + grp) * GSTR + kk * 8 + qid;
                ah[mi][0] = p[0]; ah[mi][1] = p[8 * GSTR];
                ah[mi][2] = p[4]; ah[mi][3] = p[8 * GSTR + 4];
                const unsigned* q = Asl + (wm + mi * 16 + grp) * GSTR + kk * 8 + qid;
                al[mi][0] = q[0]; al[mi][1] = q[8 * GSTR];
                al[mi][2] = q[4]; al[mi][3] = q[8 * GSTR + 4];
            }
#pragma unroll
            for (int nj = 0; nj < 4; nj++) {
                const unsigned* p = Bsh + (wn + nj * 8 + grp) * GSTR + kk * 8 + qid;
                bh[nj][0] = p[0]; bh[nj][1] = p[4];
                const unsigned* q = Bsl + (wn + nj * 8 + grp) * GSTR + kk * 8 + qid;
                bl[nj][0] = q[0]; bl[nj][1] = q[4];
            }
#pragma unroll
            for (int mi = 0; mi < 4; mi++)
#pragma unroll
                for (int nj = 0; nj < 4; nj++)
                    mma3(acc[mi][nj], ah[mi], al[mi],
                         bh[nj][0], bh[nj][1], bl[nj][0], bl[nj][1]);
        }
        __syncthreads();
        stg = (stg + 1) % 3;
    }

    // ---- epilogue ----
#pragma unroll
    for (int mi = 0; mi < 4; mi++) {
        int row0 = m0 + wm + mi * 16 + grp;
#pragma unroll
        for (int nj = 0; nj < 4; nj++) {
            int col = n0 + wn + nj * 8 + qid * 2;
            if (MODE == 0) {
                *(float2*)(C + (size_t)row0 * N + col) =
                    make_float2(acc[mi][nj][0], acc[mi][nj][1]);
                *(float2*)(C + (size_t)(row0 + 8) * N + col) =
                    make_float2(acc[mi][nj][2], acc[mi][nj][3]);
            } else {
                const int d2 = (col >> 1) & 63;
#pragma unroll
                for (int half = 0; half < 2; half++) {
                    int r = row0 + half * 8;
                    float x0 = acc[mi][nj][half * 2];
                    float x1 = acc[mi][nj][half * 2 + 1];
                    int s = r & (S_ - 1);
                    float cc = cs[s * 64 + d2];
                    float sv = sn[s * 64 + d2];
                    float o0 = x0 * cc - x1 * sv;
                    float o1 = x0 * sv + x1 * cc;
                    if (MODE == 1) {
                        const float scale = 0.08838834764831845f;
                        o0 *= scale; o1 *= scale;
                    }
                    unsigned hi, lo;
                    split2(o0, o1, hi, lo);
                    size_t o;
                    if (MODE == 1) o = (size_t)r * DP_ + (col >> 1);
                    else {
                        int b = r >> 11, ss = r & (S_ - 1), hk = col >> 7;
                        o = ((size_t)(b * HK_ + hk) * S_ + ss) * 64 + d2;
                    }
                    Oh[o] = hi; Ol[o] = lo;
                }
            }
        }
    }
}

// =====================================================================
// Flash attention, bf16x3 mma.sync, causal, GQA (unchanged from R6).
// =====================================================================
#define KSTR 68
#define VSTR 36
#define KPLU (64 * KSTR)
#define VPLU (128 * VSTR)
#define ASTGU (2 * KPLU + 2 * VPLU)
#define A_SMEM ((2 * ASTGU + 2 * VPLU) * 4)

__global__ void __launch_bounds__(256, 1) attn_mma(const unsigned* __restrict__ Qh,
                                                   const unsigned* __restrict__ Ql,
                                                   const unsigned* __restrict__ Kp,
                                                   const unsigned* __restrict__ Klp,
                                                   const unsigned* __restrict__ Vth,
                                                   const unsigned* __restrict__ Vtl,
                                                   unsigned* __restrict__ Oh,
                                                   unsigned* __restrict__ Ol)
{
    extern __shared__ unsigned smu[];
    const unsigned sm_base = s2u(smu);
    unsigned* Ph = smu + 2 * ASTGU;
    unsigned* Pl = Ph + VPLU;

    const int tid  = threadIdx.x;
    const int lane = tid & 31;
    const int warp = tid >> 5;
    const int grp  = lane >> 2;
    const int qid  = lane & 3;
    const int qt = blockIdx.x;
    const int h  = blockIdx.y;
    const int b  = blockIdx.z;
    const int hk = h >> 2;
    const int q0  = qt * 128;
    const int wq0 = warp * 16;

    const unsigned* kbh = Kp  + (size_t)(b * HK_ + hk) * S_ * 64;
    const unsigned* kbl = Klp + (size_t)(b * HK_ + hk) * S_ * 64;
    const unsigned* vbh = Vth + (size_t)(b * HK_ + hk) * HD_ * SP_;
    const unsigned* vbl = Vtl + (size_t)(b * HK_ + hk) * HD_ * SP_;

    unsigned qh[8][4], ql[8][4];
    {
        const unsigned* q0h = Qh + (size_t)(b * S_ + q0 + wq0) * DP_ + h * 64;
        const unsigned* q0l = Ql + (size_t)(b * S_ + q0 + wq0) * DP_ + h * 64;
#pragma unroll
        for (int kk = 0; kk < 8; kk++) {
            qh[kk][0] = q0h[(size_t)grp * DP_ + kk * 8 + qid];
            qh[kk][1] = q0h[(size_t)(grp + 8) * DP_ + kk * 8 + qid];
            qh[kk][2] = q0h[(size_t)grp * DP_ + kk * 8 + qid + 4];
            qh[kk][3] = q0h[(size_t)(grp + 8) * DP_ + kk * 8 + qid + 4];
            ql[kk][0] = q0l[(size_t)grp * DP_ + kk * 8 + qid];
            ql[kk][1] = q0l[(size_t)(grp + 8) * DP_ + kk * 8 + qid];
            ql[kk][2] = q0l[(size_t)grp * DP_ + kk * 8 + qid + 4];
            ql[kk][3] = q0l[(size_t)(grp + 8) * DP_ + kk * 8 + qid + 4];
        }
    }

    float o_acc[16][4];
#pragma unroll
    for (int i = 0; i < 16; i++)
#pragma unroll
        for (int c = 0; c < 4; c++) o_acc[i][c] = 0.0f;
    float m0r = -1e30f, m1r = -1e30f, l0r = 0.0f, l1r = 0.0f;

    const int qrow0 = q0 + wq0 + grp;
    const int tmax = 2 * qt + 1;

    const int krr = tid >> 2;
    const int kcc = tid & 3;
    const int vrr = tid >> 1;
    const int vcc = tid & 1;

    auto issueT = [&](int tt, int stg) {
        const unsigned sb = sm_base + (unsigned)(stg * ASTGU * 4);
        const int kv = tt * 64;
        const unsigned* gkh = kbh + (size_t)(kv + krr) * 64 + kcc * 4;
        const unsigned* gkl = kbl + (size_t)(kv + krr) * 64 + kcc * 4;
        const unsigned ks = sb + krr * (KSTR * 4) + kcc * 16;
#pragma unroll
        for (int j = 0; j < 4; j++) {
            cpa16(ks + j * 64,            gkh + j * 16);
            cpa16(ks + KPLU * 4 + j * 64, gkl + j * 16);
        }
        const unsigned* gvh = vbh + (size_t)vrr * SP_ + (kv >> 1) + vcc * 4;
        const unsigned* gvl = vbl + (size_t)vrr * SP_ + (kv >> 1) + vcc * 4;
        const unsigned vs = sb + 2 * KPLU * 4 + vrr * (VSTR * 4) + vcc * 16;
#pragma unroll
        for (int j = 0; j < 4; j++) {
            cpa16(vs + j * 32,            gvh + j * 8);
            cpa16(vs + VPLU * 4 + j * 32, gvl + j * 8);
        }
        asm volatile("cp.async.commit_group;");
    };

    issueT(0, 0);

    for (int t = 0; t <= tmax; t++) {
        const int kv0 = t * 64;
        if (t < tmax) {
            issueT(t + 1, (t + 1) & 1);
            asm volatile("cp.async.wait_group 1;");
        } else {
            asm volatile("cp.async.wait_group 0;");
        }
        __syncthreads();

        if (kv0 <= q0 + wq0 + 15) {
            const unsigned* sKh = smu + (t & 1) * ASTGU;
            const unsigned* sKl = sKh + KPLU;
            const unsigned* sVh = sKl + KPLU;
            const unsigned* sVl = sVh + VPLU;

            float s[8][4];
#pragma unroll
            for (int nj = 0; nj < 8; nj++)
#pragma unroll
                for (int c = 0; c < 4; c++) s[nj][c] = 0.0f;

#pragma unroll
            for (int kk = 0; kk < 8; kk++) {
#pragma unroll
                for (int nj = 0; nj < 8; nj++) {
                    const unsigned* ph = sKh + (nj * 8 + grp) * KSTR + kk * 8 + qid;
                    const unsigned* pl = sKl + (nj * 8 + grp) * KSTR + kk * 8 + qid;
                    mma3(s[nj], qh[kk], ql[kk], ph[0], ph[4], pl[0], pl[4]);
                }
            }

            if (kv0 + 63 > q0 + wq0) {
#pragma unroll
                for (int nj = 0; nj < 8; nj++) {
                    int kcol = kv0 + nj * 8 + 2 * qid;
                    if (kcol     > qrow0)     s[nj][0] = -1e30f;
                    if (kcol + 1 > qrow0)     s[nj][1] = -1e30f;
                    if (kcol     > qrow0 + 8) s[nj][2] = -1e30f;
                    if (kcol + 1 > qrow0 + 8) s[nj][3] = -1e30f;
                }
            }

            float rm0 = -1e30f, rm1 = -1e30f;
#pragma unroll
            for (int nj = 0; nj < 8; nj++) {
                rm0 = fmaxf(rm0, fmaxf(s[nj][0], s[nj][1]));
                rm1 = fmaxf(rm1, fmaxf(s[nj][2], s[nj][3]));
            }
            rm0 = fmaxf(rm0, __shfl_xor_sync(0xffffffffu, rm0, 1));
            rm0 = fmaxf(rm0, __shfl_xor_sync(0xffffffffu, rm0, 2));
            rm1 = fmaxf(rm1, __shfl_xor_sync(0xffffffffu, rm1, 1));
            rm1 = fmaxf(rm1, __shfl_xor_sync(0xffffffffu, rm1, 2));

            float mn0 = fmaxf(m0r, rm0), mn1 = fmaxf(m1r, rm1);
            float a0 = __expf(m0r - mn0), a1 = __expf(m1r - mn1);
            m0r = mn0; m1r = mn1;

            float rs0 = 0.0f, rs1 = 0.0f;
#pragma unroll
            for (int nj = 0; nj < 8; nj++) {
                s[nj][0] = __expf(s[nj][0] - mn0);
                s[nj][1] = __expf(s[nj][1] - mn0);
                s[nj][2] = __expf(s[nj][2] - mn1);
                s[nj][3] = __expf(s[nj][3] - mn1);
                rs0 += s[nj][0] + s[nj][1];
                rs1 += s[nj][2] + s[nj][3];
            }
            rs0 += __shfl_xor_sync(0xffffffffu, rs0, 1);
            rs0 += __shfl_xor_sync(0xffffffffu, rs0, 2);
            rs1 += __shfl_xor_sync(0xffffffffu, rs1, 1);
            rs1 += __shfl_xor_sync(0xffffffffu, rs1, 2);
            l0r = l0r * a0 + rs0;
            l1r = l1r * a1 + rs1;

#pragma unroll
            for (int nj = 0; nj < 16; nj++) {
                o_acc[nj][0] *= a0; o_acc[nj][1] *= a0;
                o_acc[nj][2] *= a1; o_acc[nj][3] *= a1;
            }

#pragma unroll
            for (int nj = 0; nj < 8; nj++) {
                unsigned hi, lo;
                split2(s[nj][0], s[nj][1], hi, lo);
                Ph[(wq0 + grp) * VSTR + nj * 4 + qid] = hi;
                Pl[(wq0 + grp) * VSTR + nj * 4 + qid] = lo;
                split2(s[nj][2], s[nj][3], hi, lo);
                Ph[(wq0 + grp + 8) * VSTR + nj * 4 + qid] = hi;
                Pl[(wq0 + grp + 8) * VSTR + nj * 4 + qid] = lo;
            }
            __syncwarp();

#pragma unroll
            for (int kk = 0; kk < 4; kk++) {
                unsigned ah[4], al[4];
                const unsigned* p0 = Ph + (wq0 + grp) * VSTR + kk * 8 + qid;
                const unsigned* p1 = Ph + (wq0 + grp + 8) * VSTR + kk * 8 + qid;
                ah[0] = p0[0]; ah[1] = p1[0]; ah[2] = p0[4]; ah[3] = p1[4];
                const unsigned* q0p = Pl + (wq0 + grp) * VSTR + kk * 8 + qid;
                const unsigned* q1p = Pl + (wq0 + grp + 8) * VSTR + kk * 8 + qid;
                al[0] = q0p[0]; al[1] = q1p[0]; al[2] = q0p[4]; al[3] = q1p[4];
#pragma unroll
                for (int nj = 0; nj < 16; nj++) {
                    const unsigned* bh = sVh + (nj * 8 + grp) * VSTR + kk * 8 + qid;
                    const unsigned* bl = sVl + (nj * 8 + grp) * VSTR + kk * 8 + qid;
                    mma3(o_acc[nj], ah, al, bh[0], bh[4], bl[0], bl[4]);
                }
            }
        }
        __syncthreads();
    }

    const float il0 = 1.0f / l0r;
    const float il1 = 1.0f / l1r;
    const size_t r0 = (size_t)(b * S_ + q0 + wq0 + grp) * DP_;
    const size_t r1 = (size_t)(b * S_ + q0 + wq0 + grp + 8) * DP_;
#pragma unroll
    for (int nj = 0; nj < 16; nj++) {
        int col = h * 64 + nj * 4 + qid;
        unsigned hi, lo;
        split2(o_acc[nj][0] * il0, o_acc[nj][1] * il0, hi, lo);
        Oh[r0 + col] = hi; Ol[r0 + col] = lo;
        split2(o_acc[nj][2] * il1, o_acc[nj][3] * il1, hi, lo);
        Oh[r1 + col] = hi; Ol[r1 + col] = lo;
    }
}

// =====================================================================
// launch
// =====================================================================
extern "C" void kernel_launch(void* const* d_in, const int* in_sizes, int n_in,
                              void* d_out, int out_size)
{
    const float* x  = (const float*)d_in[0];
    const float* fc = (const float*)d_in[1];
    const float* fs = (const float*)d_in[2];
    const float* wq = (const float*)d_in[3];
    const float* wk = (const float*)d_in[4];
    const float* wv = (const float*)d_in[5];
    const float* wo = (const float*)d_in[6];
    float* out = (float*)d_out;

    float *v;
    unsigned *xh, *xl, *wqh, *wql, *wkh, *wkl, *wvh, *wvl, *woh, *wol, *ah, *al;
    unsigned *qh, *ql, *khp, *klp, *vth, *vtl;
    cudaGetSymbolAddress((void**)&v,   g_v);
    cudaGetSymbolAddress((void**)&xh,  g_xh);  cudaGetSymbolAddress((void**)&xl,  g_xl);
    cudaGetSymbolAddress((void**)&wqh, g_wqh); cudaGetSymbolAddress((void**)&wql, g_wql);
    cudaGetSymbolAddress((void**)&wkh, g_wkh); cudaGetSymbolAddress((void**)&wkl, g_wkl);
    cudaGetSymbolAddress((void**)&wvh, g_wvh); cudaGetSymbolAddress((void**)&wvl, g_wvl);
    cudaGetSymbolAddress((void**)&woh, g_woh); cudaGetSymbolAddress((void**)&wol, g_wol);
    cudaGetSymbolAddress((void**)&ah,  g_ah);  cudaGetSymbolAddress((void**)&al,  g_al);
    cudaGetSymbolAddress((void**)&qh,  g_qh);  cudaGetSymbolAddress((void**)&ql,  g_ql);
    cudaGetSymbolAddress((void**)&khp, g_khp); cudaGetSymbolAddress((void**)&klp, g_klp);
    cudaGetSymbolAddress((void**)&vth, g_vth); cudaGetSymbolAddress((void**)&vtl, g_vtl);

    // input splits
    {
        int np;
        np = M_ * DP_;   split_kernel<<<np / 256, 256>>>(x,  xh,  xl,  np);
        np = D_ * DP_;   split_kernel<<<np / 256, 256>>>(wq, wqh, wql, np);
        np = KVD_ * DP_; split_kernel<<<np / 256, 256>>>(wk, wkh, wkl, np);
        np = KVD_ * DP_; split_kernel<<<np / 256, 256>>>(wv, wvh, wvl, np);
        np = D_ * DP_;   split_kernel<<<np / 256, 256>>>(wo, woh, wol, np);
    }

    cudaFuncSetAttribute(gemm3<0>, cudaFuncAttributeMaxDynamicSharedMemorySize, G_SMEM);
    cudaFuncSetAttribute(gemm3<1>, cudaFuncAttributeMaxDynamicSharedMemorySize, G_SMEM);
    cudaFuncSetAttribute(gemm3<2>, cudaFuncAttributeMaxDynamicSharedMemorySize, G_SMEM);

    // projections (Q,K with fused rope+split epilogue; V plain fp32)
    gemm3<1><<<dim3(32, 16), 512, G_SMEM>>>(xh, xl, wqh, wql, nullptr, qh, ql, fc, fs, D_, D_);
    gemm3<2><<<dim3(8,  16), 512, G_SMEM>>>(xh, xl, wkh, wkl, nullptr, khp, klp, fc, fs, KVD_, D_);
    gemm3<0><<<dim3(8,  16), 512, G_SMEM>>>(xh, xl, wvh, wvl, v, nullptr, nullptr, nullptr, nullptr, KVD_, D_);

    // V transpose+split
    transpose_split_v<<<dim3(S_ / 64, HK_, B_), 256>>>(v, vth, vtl);

    // attention
    cudaFuncSetAttribute(attn_mma, cudaFuncAttributeMaxDynamicSharedMemorySize, A_SMEM);
    attn_mma<<<dim3(S_ / 128, H_, B_), 256, A_SMEM>>>(qh, ql, khp, klp, vth, vtl, ah, al);

    // output projection
    gemm3<0><<<dim3(32, 16), 512, G_SMEM>>>(ah, al, woh, wol, out, nullptr, nullptr, nullptr, nullptr, D_, D_);
}

// round 8
// speedup vs baseline: 2.1185x; 1.8123x over previous
#include <cuda_runtime.h>
#include <cuda_bf16.h>
#include <cuda_fp16.h>
#include <cstdint>
#include <math.h>

#define B_   2
#define S_   2048
#define D_   4096
#define H_   32
#define HK_  8
#define HD_  128
#define M_   (B_ * S_)          // 4096 total tokens
#define KVD_ (HK_ * HD_)        // 1024
#define DP_  (D_ / 2)           // 2048 u32 pairs per row
#define SP_  (S_ / 2)           // 1024 seq pairs

// ---------------- scratch (device globals; no allocation allowed) ----------------
__device__ float    g_v[(size_t)M_ * KVD_];
// fp16 packed pair planes (operands for projections)
__device__ unsigned g_x16[(size_t)M_ * DP_];
__device__ unsigned g_wq16[(size_t)D_ * DP_];
__device__ unsigned g_wk16[(size_t)KVD_ * DP_];
__device__ unsigned g_wv16[(size_t)KVD_ * DP_];
__device__ unsigned g_wo16[(size_t)D_ * DP_];
__device__ unsigned g_af16[(size_t)M_ * DP_];   // attention out (fp16 pairs)
// attention operand planes (bf16 hi/lo, unchanged path)
__device__ unsigned g_qh[(size_t)M_ * DP_],   g_ql[(size_t)M_ * DP_];
__device__ unsigned g_khp[(size_t)B_ * HK_ * S_ * 64], g_klp[(size_t)B_ * HK_ * S_ * 64];
__device__ unsigned g_vth[(size_t)B_ * HK_ * HD_ * SP_], g_vtl[(size_t)B_ * HK_ * HD_ * SP_];

// ---------------- helpers ----------------
__device__ __forceinline__ void split2(float x, float y, unsigned& hi, unsigned& lo) {
    __nv_bfloat16 xh = __float2bfloat16_rn(x);
    __nv_bfloat16 yh = __float2bfloat16_rn(y);
    __nv_bfloat16 xl = __float2bfloat16_rn(x - __bfloat162float(xh));
    __nv_bfloat16 yl = __float2bfloat16_rn(y - __bfloat162float(yh));
    hi = (unsigned)__bfloat16_as_ushort(xh) | ((unsigned)__bfloat16_as_ushort(yh) << 16);
    lo = (unsigned)__bfloat16_as_ushort(xl) | ((unsigned)__bfloat16_as_ushort(yl) << 16);
}

__device__ __forceinline__ unsigned packh2(float x, float y) {
    __half2 h = __floats2half2_rn(x, y);
    return *reinterpret_cast<unsigned*>(&h);
}

__device__ __forceinline__ void mma_bf16(float* c, const unsigned* a, unsigned b0, unsigned b1) {
    asm volatile(
        "mma.sync.aligned.m16n8k16.row.col.f32.bf16.bf16.f32 "
        "{%0,%1,%2,%3}, {%4,%5,%6,%7}, {%8,%9}, {%0,%1,%2,%3};\n"
        : "+f"(c[0]), "+f"(c[1]), "+f"(c[2]), "+f"(c[3])
        : "r"(a[0]), "r"(a[1]), "r"(a[2]), "r"(a[3]), "r"(b0), "r"(b1));
}

__device__ __forceinline__ void mma_fp16(float* c, const unsigned* a, unsigned b0, unsigned b1) {
    asm volatile(
        "mma.sync.aligned.m16n8k16.row.col.f32.f16.f16.f32 "
        "{%0,%1,%2,%3}, {%4,%5,%6,%7}, {%8,%9}, {%0,%1,%2,%3};\n"
        : "+f"(c[0]), "+f"(c[1]), "+f"(c[2]), "+f"(c[3])
        : "r"(a[0]), "r"(a[1]), "r"(a[2]), "r"(a[3]), "r"(b0), "r"(b1));
}

__device__ __forceinline__ void mma3(float* c, const unsigned* ah, const unsigned* al,
                                     unsigned b0h, unsigned b1h, unsigned b0l, unsigned b1l) {
    mma_bf16(c, ah, b0h, b1h);
    mma_bf16(c, ah, b0l, b1l);
    mma_bf16(c, al, b0h, b1h);
}

__device__ __forceinline__ void cpa16(unsigned saddr, const void* g) {
    asm volatile("cp.async.cg.shared.global [%0], [%1], 16;" :: "r"(saddr), "l"(g));
}

__device__ __forceinline__ uint32_t s2u(const void* p) {
    uint32_t a;
    asm("{ .reg .u64 t; cvta.to.shared.u64 t, %1; cvt.u32.u64 %0, t; }" : "=r"(a) : "l"(p));
    return a;
}

// ---------------- pack pass: fp32 -> fp16 pair plane ----------------
__global__ void pack16_kernel(const float* __restrict__ X,
                              unsigned* __restrict__ O, int npairs)
{
    int i = blockIdx.x * blockDim.x + threadIdx.x;
    if (i >= npairs) return;
    float2 v = ((const float2*)X)[i];
    O[i] = packh2(v.x, v.y);
}

// ---------------- transpose + split V -> bf16 planes [b,hk,d,s-pairs] ----------------
__global__ void __launch_bounds__(256) transpose_split_v(const float* __restrict__ V,
                                                         unsigned* __restrict__ Oh,
                                                         unsigned* __restrict__ Ol)
{
    __shared__ float sm[64 * 132];
    const int tid = threadIdx.x;
    const int s0  = blockIdx.x * 64;
    const int hk  = blockIdx.y;
    const int b   = blockIdx.z;

#pragma unroll
    for (int i = 0; i < 32; i++) {
        int idx = tid + i * 256;
        int r = idx >> 7, c = idx & 127;
        sm[r * 132 + c] = V[(size_t)(b * S_ + s0 + r) * KVD_ + hk * HD_ + c];
    }
    __syncthreads();

    const int d  = tid >> 1;
    const int pb = (tid & 1) * 16;
    unsigned* oh = Oh + ((size_t)(b * HK_ + hk) * HD_ + d) * SP_ + (s0 >> 1) + pb;
    unsigned* ol = Ol + ((size_t)(b * HK_ + hk) * HD_ + d) * SP_ + (s0 >> 1) + pb;
#pragma unroll
    for (int i = 0; i < 16; i++) {
        int p = pb + i;
        float f0 = sm[(2 * p) * 132 + d];
        float f1 = sm[(2 * p + 1) * 132 + d];
        unsigned hi, lo;
        split2(f0, f1, hi, lo);
        oh[i] = hi; ol[i] = lo;
    }
}

// =====================================================================
// fp16 single-stream GEMM: C[M,N] = A[M,K]*B[N,K]^T (fp16 pair planes)
// CTA tile 256x128, BK=64 (32 pairs), 512 threads = 16 warps (4x4 of
// 64x32 warp tiles), 3-stage cp.async.
// MODE 0: fp32 C. MODE 1: rope+scale+bf16split -> Q planes [row][DP_].
// MODE 2: rope+bf16split -> K planes [b,hk,s,64].
// =====================================================================
#define GSTR 36                       // smem row stride (u32): 32 data + 4 pad
#define APLU (256 * GSTR)             // 9216 u32
#define BPLU (128 * GSTR)             // 4608 u32
#define GSTGU (APLU + BPLU)           // 13824 u32 per stage
#define G_SMEM (3 * GSTGU * 4)        // 165888 B

template <int MODE>
__global__ void __launch_bounds__(512, 1)
gemm16(const unsigned* __restrict__ Ap, const unsigned* __restrict__ Bp,
       float* __restrict__ C, unsigned* __restrict__ Oh, unsigned* __restrict__ Ol,
       const float* __restrict__ cs, const float* __restrict__ sn,
       int N, int K)
{
    extern __shared__ unsigned gs[];

    const int tid  = threadIdx.x;
    const int lane = tid & 31;
    const int warp = tid >> 5;
    const int m0 = blockIdx.y << 8;
    const int n0 = blockIdx.x << 7;
    const int wm = (warp >> 2) * 64;
    const int wn = (warp & 3) * 32;
    const int grp = lane >> 2;
    const int qid = lane & 3;
    const int KP = K >> 1;

    // cp.async mapping (per 64-element chunk: A row 128B, B row 128B)
    const int lra = tid >> 1;                 // A row 0..255
    const int lca = (tid & 1) * 16;           // u32 offset 0/16
    const int lrb = tid >> 2;                 // B row 0..127
    const int lcb = (tid & 3) * 8;            // u32 offset 0..24
    const unsigned* ag = Ap + (size_t)(m0 + lra) * KP + lca;
    const unsigned* bg = Bp + (size_t)(n0 + lrb) * KP + lcb;

    const unsigned sbase = s2u(gs);
    const unsigned sra = (lra * GSTR + lca) * 4;
    const unsigned srb = (lrb * GSTR + lcb) * 4;

    float acc[4][4][4];
#pragma unroll
    for (int i = 0; i < 4; i++)
#pragma unroll
        for (int j = 0; j < 4; j++)
#pragma unroll
            for (int c = 0; c < 4; c++) acc[i][j][c] = 0.0f;

    const int nch = K / 64;

    auto issue = [&](int c, int stg) {
        unsigned sb = sbase + (unsigned)(stg * GSTGU * 4);
        const int go = c * 32;
        cpa16(sb + sra,                ag + go);
        cpa16(sb + sra + 16,           ag + go + 4);
        cpa16(sb + sra + 32,           ag + go + 8);
        cpa16(sb + sra + 48,           ag + go + 12);
        cpa16(sb + APLU * 4 + srb,       bg + go);
        cpa16(sb + APLU * 4 + srb + 16,  bg + go + 4);
        asm volatile("cp.async.commit_group;");
    };

    issue(0, 0);
    if (nch > 1) issue(1, 1);

    int stg = 0;
    for (int c = 0; c < nch; c++) {
        if (c + 2 < nch) issue(c + 2, (stg + 2) % 3);
        const int rem = nch - 1 - c;
        if (rem >= 2)      { asm volatile("cp.async.wait_group 2;"); }
        else if (rem == 1) { asm volatile("cp.async.wait_group 1;"); }
        else               { asm volatile("cp.async.wait_group 0;"); }
        __syncthreads();

        const unsigned* Ash = gs + stg * GSTGU;
        const unsigned* Bsh = Ash + APLU;

#pragma unroll
        for (int kk = 0; kk < 4; kk++) {
            unsigned af[4][4], bf[4][2];
#pragma unroll
            for (int mi = 0; mi < 4; mi++) {
                const unsigned* p = Ash + (wm + mi * 16 + grp) * GSTR + kk * 8 + qid;
                af[mi][0] = p[0]; af[mi][1] = p[8 * GSTR];
                af[mi][2] = p[4]; af[mi][3] = p[8 * GSTR + 4];
            }
#pragma unroll
            for (int nj = 0; nj < 4; nj++) {
                const unsigned* p = Bsh + (wn + nj * 8 + grp) * GSTR + kk * 8 + qid;
                bf[nj][0] = p[0]; bf[nj][1] = p[4];
            }
#pragma unroll
            for (int mi = 0; mi < 4; mi++)
#pragma unroll
                for (int nj = 0; nj < 4; nj++)
                    mma_fp16(acc[mi][nj], af[mi], bf[nj][0], bf[nj][1]);
        }
        __syncthreads();
        stg = (stg + 1) % 3;
    }

    // ---- epilogue ----
#pragma unroll
    for (int mi = 0; mi < 4; mi++) {
        int row0 = m0 + wm + mi * 16 + grp;
#pragma unroll
        for (int nj = 0; nj < 4; nj++) {
            int col = n0 + wn + nj * 8 + qid * 2;
            if (MODE == 0) {
                *(float2*)(C + (size_t)row0 * N + col) =
                    make_float2(acc[mi][nj][0], acc[mi][nj][1]);
                *(float2*)(C + (size_t)(row0 + 8) * N + col) =
                    make_float2(acc[mi][nj][2], acc[mi][nj][3]);
            } else {
                const int d2 = (col >> 1) & 63;
#pragma unroll
                for (int half = 0; half < 2; half++) {
                    int r = row0 + half * 8;
                    float x0 = acc[mi][nj][half * 2];
                    float x1 = acc[mi][nj][half * 2 + 1];
                    int s = r & (S_ - 1);
                    float cc = cs[s * 64 + d2];
                    float sv = sn[s * 64 + d2];
                    float o0 = x0 * cc - x1 * sv;
                    float o1 = x0 * sv + x1 * cc;
                    if (MODE == 1) {
                        const float scale = 0.08838834764831845f;
                        o0 *= scale; o1 *= scale;
                    }
                    unsigned hi, lo;
                    split2(o0, o1, hi, lo);
                    size_t o;
                    if (MODE == 1) o = (size_t)r * DP_ + (col >> 1);
                    else {
                        int b = r >> 11, ss = r & (S_ - 1), hk = col >> 7;
                        o = ((size_t)(b * HK_ + hk) * S_ + ss) * 64 + d2;
                    }
                    Oh[o] = hi; Ol[o] = lo;
                }
            }
        }
    }
}

// =====================================================================
// Flash attention, bf16x3 mma.sync, causal, GQA (R7 core; fp16 output).
// =====================================================================
#define KSTR 68
#define VSTR 36
#define KPLU (64 * KSTR)
#define VPLU (128 * VSTR)
#define ASTGU (2 * KPLU + 2 * VPLU)
#define A_SMEM ((2 * ASTGU + 2 * VPLU) * 4)

__global__ void __launch_bounds__(256, 1) attn_mma(const unsigned* __restrict__ Qh,
                                                   const unsigned* __restrict__ Ql,
                                                   const unsigned* __restrict__ Kp,
                                                   const unsigned* __restrict__ Klp,
                                                   const unsigned* __restrict__ Vth,
                                                   const unsigned* __restrict__ Vtl,
                                                   unsigned* __restrict__ Of16)
{
    extern __shared__ unsigned smu[];
    const unsigned sm_base = s2u(smu);
    unsigned* Ph = smu + 2 * ASTGU;
    unsigned* Pl = Ph + VPLU;

    const int tid  = threadIdx.x;
    const int lane = tid & 31;
    const int warp = tid >> 5;
    const int grp  = lane >> 2;
    const int qid  = lane & 3;
    const int qt = blockIdx.x;
    const int h  = blockIdx.y;
    const int b  = blockIdx.z;
    const int hk = h >> 2;
    const int q0  = qt * 128;
    const int wq0 = warp * 16;

    const unsigned* kbh = Kp  + (size_t)(b * HK_ + hk) * S_ * 64;
    const unsigned* kbl = Klp + (size_t)(b * HK_ + hk) * S_ * 64;
    const unsigned* vbh = Vth + (size_t)(b * HK_ + hk) * HD_ * SP_;
    const unsigned* vbl = Vtl + (size_t)(b * HK_ + hk) * HD_ * SP_;

    unsigned qh[8][4], ql[8][4];
    {
        const unsigned* q0h = Qh + (size_t)(b * S_ + q0 + wq0) * DP_ + h * 64;
        const unsigned* q0l = Ql + (size_t)(b * S_ + q0 + wq0) * DP_ + h * 64;
#pragma unroll
        for (int kk = 0; kk < 8; kk++) {
            qh[kk][0] = q0h[(size_t)grp * DP_ + kk * 8 + qid];
            qh[kk][1] = q0h[(size_t)(grp + 8) * DP_ + kk * 8 + qid];
            qh[kk][2] = q0h[(size_t)grp * DP_ + kk * 8 + qid + 4];
            qh[kk][3] = q0h[(size_t)(grp + 8) * DP_ + kk * 8 + qid + 4];
            ql[kk][0] = q0l[(size_t)grp * DP_ + kk * 8 + qid];
            ql[kk][1] = q0l[(size_t)(grp + 8) * DP_ + kk * 8 + qid];
            ql[kk][2] = q0l[(size_t)grp * DP_ + kk * 8 + qid + 4];
            ql[kk][3] = q0l[(size_t)(grp + 8) * DP_ + kk * 8 + qid + 4];
        }
    }

    float o_acc[16][4];
#pragma unroll
    for (int i = 0; i < 16; i++)
#pragma unroll
        for (int c = 0; c < 4; c++) o_acc[i][c] = 0.0f;
    float m0r = -1e30f, m1r = -1e30f, l0r = 0.0f, l1r = 0.0f;

    const int qrow0 = q0 + wq0 + grp;
    const int tmax = 2 * qt + 1;

    const int krr = tid >> 2;
    const int kcc = tid & 3;
    const int vrr = tid >> 1;
    const int vcc = tid & 1;

    auto issueT = [&](int tt, int stg) {
        const unsigned sb = sm_base + (unsigned)(stg * ASTGU * 4);
        const int kv = tt * 64;
        const unsigned* gkh = kbh + (size_t)(kv + krr) * 64 + kcc * 4;
        const unsigned* gkl = kbl + (size_t)(kv + krr) * 64 + kcc * 4;
        const unsigned ks = sb + krr * (KSTR * 4) + kcc * 16;
#pragma unroll
        for (int j = 0; j < 4; j++) {
            cpa16(ks + j * 64,            gkh + j * 16);
            cpa16(ks + KPLU * 4 + j * 64, gkl + j * 16);
        }
        const unsigned* gvh = vbh + (size_t)vrr * SP_ + (kv >> 1) + vcc * 4;
        const unsigned* gvl = vbl + (size_t)vrr * SP_ + (kv >> 1) + vcc * 4;
        const unsigned vs = sb + 2 * KPLU * 4 + vrr * (VSTR * 4) + vcc * 16;
#pragma unroll
        for (int j = 0; j < 4; j++) {
            cpa16(vs + j * 32,            gvh + j * 8);
            cpa16(vs + VPLU * 4 + j * 32, gvl + j * 8);
        }
        asm volatile("cp.async.commit_group;");
    };

    issueT(0, 0);

    for (int t = 0; t <= tmax; t++) {
        const int kv0 = t * 64;
        if (t < tmax) {
            issueT(t + 1, (t + 1) & 1);
            asm volatile("cp.async.wait_group 1;");
        } else {
            asm volatile("cp.async.wait_group 0;");
        }
        __syncthreads();

        if (kv0 <= q0 + wq0 + 15) {
            const unsigned* sKh = smu + (t & 1) * ASTGU;
            const unsigned* sKl = sKh + KPLU;
            const unsigned* sVh = sKl + KPLU;
            const unsigned* sVl = sVh + VPLU;

            float s[8][4];
#pragma unroll
            for (int nj = 0; nj < 8; nj++)
#pragma unroll
                for (int c = 0; c < 4; c++) s[nj][c] = 0.0f;

#pragma unroll
            for (int kk = 0; kk < 8; kk++) {
#pragma unroll
                for (int nj = 0; nj < 8; nj++) {
                    const unsigned* ph = sKh + (nj * 8 + grp) * KSTR + kk * 8 + qid;
                    const unsigned* pl = sKl + (nj * 8 + grp) * KSTR + kk * 8 + qid;
                    mma3(s[nj], qh[kk], ql[kk], ph[0], ph[4], pl[0], pl[4]);
                }
            }

            if (kv0 + 63 > q0 + wq0) {
#pragma unroll
                for (int nj = 0; nj < 8; nj++) {
                    int kcol = kv0 + nj * 8 + 2 * qid;
                    if (kcol     > qrow0)     s[nj][0] = -1e30f;
                    if (kcol + 1 > qrow0)     s[nj][1] = -1e30f;
                    if (kcol     > qrow0 + 8) s[nj][2] = -1e30f;
                    if (kcol + 1 > qrow0 + 8) s[nj][3] = -1e30f;
                }
            }

            float rm0 = -1e30f, rm1 = -1e30f;
#pragma unroll
            for (int nj = 0; nj < 8; nj++) {
                rm0 = fmaxf(rm0, fmaxf(s[nj][0], s[nj][1]));
                rm1 = fmaxf(rm1, fmaxf(s[nj][2], s[nj][3]));
            }
            rm0 = fmaxf(rm0, __shfl_xor_sync(0xffffffffu, rm0, 1));
            rm0 = fmaxf(rm0, __shfl_xor_sync(0xffffffffu, rm0, 2));
            rm1 = fmaxf(rm1, __shfl_xor_sync(0xffffffffu, rm1, 1));
            rm1 = fmaxf(rm1, __shfl_xor_sync(0xffffffffu, rm1, 2));

            float mn0 = fmaxf(m0r, rm0), mn1 = fmaxf(m1r, rm1);
            float a0 = __expf(m0r - mn0), a1 = __expf(m1r - mn1);
            m0r = mn0; m1r = mn1;

            float rs0 = 0.0f, rs1 = 0.0f;
#pragma unroll
            for (int nj = 0; nj < 8; nj++) {
                s[nj][0] = __expf(s[nj][0] - mn0);
                s[nj][1] = __expf(s[nj][1] - mn0);
                s[nj][2] = __expf(s[nj][2] - mn1);
                s[nj][3] = __expf(s[nj][3] - mn1);
                rs0 += s[nj][0] + s[nj][1];
                rs1 += s[nj][2] + s[nj][3];
            }
            rs0 += __shfl_xor_sync(0xffffffffu, rs0, 1);
            rs0 += __shfl_xor_sync(0xffffffffu, rs0, 2);
            rs1 += __shfl_xor_sync(0xffffffffu, rs1, 1);
            rs1 += __shfl_xor_sync(0xffffffffu, rs1, 2);
            l0r = l0r * a0 + rs0;
            l1r = l1r * a1 + rs1;

#pragma unroll
            for (int nj = 0; nj < 16; nj++) {
                o_acc[nj][0] *= a0; o_acc[nj][1] *= a0;
                o_acc[nj][2] *= a1; o_acc[nj][3] *= a1;
            }

#pragma unroll
            for (int nj = 0; nj < 8; nj++) {
                unsigned hi, lo;
                split2(s[nj][0], s[nj][1], hi, lo);
                Ph[(wq0 + grp) * VSTR + nj * 4 + qid] = hi;
                Pl[(wq0 + grp) * VSTR + nj * 4 + qid] = lo;
                split2(s[nj][2], s[nj][3], hi, lo);
                Ph[(wq0 + grp + 8) * VSTR + nj * 4 + qid] = hi;
                Pl[(wq0 + grp + 8) * VSTR + nj * 4 + qid] = lo;
            }
            __syncwarp();

#pragma unroll
            for (int kk = 0; kk < 4; kk++) {
                unsigned ah[4], al[4];
                const unsigned* p0 = Ph + (wq0 + grp) * VSTR + kk * 8 + qid;
                const unsigned* p1 = Ph + (wq0 + grp + 8) * VSTR + kk * 8 + qid;
                ah[0] = p0[0]; ah[1] = p1[0]; ah[2] = p0[4]; ah[3] = p1[4];
                const unsigned* q0p = Pl + (wq0 + grp) * VSTR + kk * 8 + qid;
                const unsigned* q1p = Pl + (wq0 + grp + 8) * VSTR + kk * 8 + qid;
                al[0] = q0p[0]; al[1] = q1p[0]; al[2] = q0p[4]; al[3] = q1p[4];
#pragma unroll
                for (int nj = 0; nj < 16; nj++) {
                    const unsigned* bh = sVh + (nj * 8 + grp) * VSTR + kk * 8 + qid;
                    const unsigned* bl = sVl + (nj * 8 + grp) * VSTR + kk * 8 + qid;
                    mma3(o_acc[nj], ah, al, bh[0], bh[4], bl[0], bl[4]);
                }
            }
        }
        __syncthreads();
    }

    const float il0 = 1.0f / l0r;
    const float il1 = 1.0f / l1r;
    const size_t r0 = (size_t)(b * S_ + q0 + wq0 + grp) * DP_;
    const size_t r1 = (size_t)(b * S_ + q0 + wq0 + grp + 8) * DP_;
#pragma unroll
    for (int nj = 0; nj < 16; nj++) {
        int col = h * 64 + nj * 4 + qid;
        Of16[r0 + col] = packh2(o_acc[nj][0] * il0, o_acc[nj][1] * il0);
        Of16[r1 + col] = packh2(o_acc[nj][2] * il1, o_acc[nj][3] * il1);
    }
}

// =====================================================================
// launch
// =====================================================================
extern "C" void kernel_launch(void* const* d_in, const int* in_sizes, int n_in,
                              void* d_out, int out_size)
{
    const float* x  = (const float*)d_in[0];
    const float* fc = (const float*)d_in[1];
    const float* fs = (const float*)d_in[2];
    const float* wq = (const float*)d_in[3];
    const float* wk = (const float*)d_in[4];
    const float* wv = (const float*)d_in[5];
    const float* wo = (const float*)d_in[6];
    float* out = (float*)d_out;

    float *v;
    unsigned *x16, *wq16, *wk16, *wv16, *wo16, *af16;
    unsigned *qh, *ql, *khp, *klp, *vth, *vtl;
    cudaGetSymbolAddress((void**)&v,    g_v);
    cudaGetSymbolAddress((void**)&x16,  g_x16);
    cudaGetSymbolAddress((void**)&wq16, g_wq16);
    cudaGetSymbolAddress((void**)&wk16, g_wk16);
    cudaGetSymbolAddress((void**)&wv16, g_wv16);
    cudaGetSymbolAddress((void**)&wo16, g_wo16);
    cudaGetSymbolAddress((void**)&af16, g_af16);
    cudaGetSymbolAddress((void**)&qh,  g_qh);  cudaGetSymbolAddress((void**)&ql,  g_ql);
    cudaGetSymbolAddress((void**)&khp, g_khp); cudaGetSymbolAddress((void**)&klp, g_klp);
    cudaGetSymbolAddress((void**)&vth, g_vth); cudaGetSymbolAddress((void**)&vtl, g_vtl);

    // fp16 packs
    {
        int np;
        np = M_ * DP_;   pack16_kernel<<<np / 256, 256>>>(x,  x16,  np);
        np = D_ * DP_;   pack16_kernel<<<np / 256, 256>>>(wq, wq16, np);
        np = KVD_ * DP_; pack16_kernel<<<np / 256, 256>>>(wk, wk16, np);
        np = KVD_ * DP_; pack16_kernel<<<np / 256, 256>>>(wv, wv16, np);
        np = D_ * DP_;   pack16_kernel<<<np / 256, 256>>>(wo, wo16, np);
    }

    cudaFuncSetAttribute(gemm16<0>, cudaFuncAttributeMaxDynamicSharedMemorySize, G_SMEM);
    cudaFuncSetAttribute(gemm16<1>, cudaFuncAttributeMaxDynamicSharedMemorySize, G_SMEM);
    cudaFuncSetAttribute(gemm16<2>, cudaFuncAttributeMaxDynamicSharedMemorySize, G_SMEM);

    // projections (fp16 single-stream; Q,K with fused rope+bf16split epilogue)
    gemm16<1><<<dim3(32, 16), 512, G_SMEM>>>(x16, wq16, nullptr, qh, ql, fc, fs, D_, D_);
    gemm16<2><<<dim3(8,  16), 512, G_SMEM>>>(x16, wk16, nullptr, khp, klp, fc, fs, KVD_, D_);
    gemm16<0><<<dim3(8,  16), 512, G_SMEM>>>(x16, wv16, v, nullptr, nullptr, nullptr, nullptr, KVD_, D_);

    // V transpose+split (bf16 planes)
    transpose_split_v<<<dim3(S_ / 64, HK_, B_), 256>>>(v, vth, vtl);

    // attention (bf16x3 core, fp16 output plane)
    cudaFuncSetAttribute(attn_mma, cudaFuncAttributeMaxDynamicSharedMemorySize, A_SMEM);
    attn_mma<<<dim3(S_ / 128, H_, B_), 256, A_SMEM>>>(qh, ql, khp, klp, vth, vtl, af16);

    // output projection (fp16 single-stream)
    gemm16<0><<<dim3(32, 16), 512, G_SMEM>>>(af16, wo16, out, nullptr, nullptr, nullptr, nullptr, D_, D_);
}

// round 9
// speedup vs baseline: 2.2085x; 1.0425x over previous
#include <cuda_runtime.h>
#include <cuda_bf16.h>
#include <cuda_fp16.h>
#include <cstdint>
#include <math.h>

#define B_   2
#define S_   2048
#define D_   4096
#define H_   32
#define HK_  8
#define HD_  128
#define M_   (B_ * S_)          // 4096 total tokens
#define KVD_ (HK_ * HD_)        // 1024
#define DP_  (D_ / 2)           // 2048 u32 pairs per row
#define SP_  (S_ / 2)           // 1024 seq pairs

// ---------------- scratch (device globals; no allocation allowed) ----------------
__device__ float    g_v[(size_t)M_ * KVD_];
// fp16 packed pair planes (operands for projections)
__device__ unsigned g_x16[(size_t)M_ * DP_];
__device__ unsigned g_wq16[(size_t)D_ * DP_];
__device__ unsigned g_wk16[(size_t)KVD_ * DP_];
__device__ unsigned g_wv16[(size_t)KVD_ * DP_];
__device__ unsigned g_wo16[(size_t)D_ * DP_];
__device__ unsigned g_af16[(size_t)M_ * DP_];   // attention out (fp16 pairs)
// attention operand planes (bf16 hi/lo)
__device__ unsigned g_qh[(size_t)M_ * DP_],   g_ql[(size_t)M_ * DP_];
__device__ unsigned g_khp[(size_t)B_ * HK_ * S_ * 64], g_klp[(size_t)B_ * HK_ * S_ * 64];
__device__ unsigned g_vth[(size_t)B_ * HK_ * HD_ * SP_], g_vtl[(size_t)B_ * HK_ * HD_ * SP_];

// ---------------- helpers ----------------
__device__ __forceinline__ void split2(float x, float y, unsigned& hi, unsigned& lo) {
    __nv_bfloat16 xh = __float2bfloat16_rn(x);
    __nv_bfloat16 yh = __float2bfloat16_rn(y);
    __nv_bfloat16 xl = __float2bfloat16_rn(x - __bfloat162float(xh));
    __nv_bfloat16 yl = __float2bfloat16_rn(y - __bfloat162float(yh));
    hi = (unsigned)__bfloat16_as_ushort(xh) | ((unsigned)__bfloat16_as_ushort(yh) << 16);
    lo = (unsigned)__bfloat16_as_ushort(xl) | ((unsigned)__bfloat16_as_ushort(yl) << 16);
}

__device__ __forceinline__ unsigned packh2(float x, float y) {
    __half2 h = __floats2half2_rn(x, y);
    return *reinterpret_cast<unsigned*>(&h);
}

__device__ __forceinline__ void mma_bf16(float* c, const unsigned* a, unsigned b0, unsigned b1) {
    asm volatile(
        "mma.sync.aligned.m16n8k16.row.col.f32.bf16.bf16.f32 "
        "{%0,%1,%2,%3}, {%4,%5,%6,%7}, {%8,%9}, {%0,%1,%2,%3};\n"
        : "+f"(c[0]), "+f"(c[1]), "+f"(c[2]), "+f"(c[3])
        : "r"(a[0]), "r"(a[1]), "r"(a[2]), "r"(a[3]), "r"(b0), "r"(b1));
}

__device__ __forceinline__ void mma_fp16(float* c, const unsigned* a, unsigned b0, unsigned b1) {
    asm volatile(
        "mma.sync.aligned.m16n8k16.row.col.f32.f16.f16.f32 "
        "{%0,%1,%2,%3}, {%4,%5,%6,%7}, {%8,%9}, {%0,%1,%2,%3};\n"
        : "+f"(c[0]), "+f"(c[1]), "+f"(c[2]), "+f"(c[3])
        : "r"(a[0]), "r"(a[1]), "r"(a[2]), "r"(a[3]), "r"(b0), "r"(b1));
}

__device__ __forceinline__ void mma3(float* c, const unsigned* ah, const unsigned* al,
                                     unsigned b0h, unsigned b1h, unsigned b0l, unsigned b1l) {
    mma_bf16(c, ah, b0h, b1h);
    mma_bf16(c, ah, b0l, b1l);
    mma_bf16(c, al, b0h, b1h);
}

__device__ __forceinline__ void cpa16(unsigned saddr, const void* g) {
    asm volatile("cp.async.cg.shared.global [%0], [%1], 16;" :: "r"(saddr), "l"(g));
}

__device__ __forceinline__ uint32_t s2u(const void* p) {
    uint32_t a;
    asm("{ .reg .u64 t; cvta.to.shared.u64 t, %1; cvt.u32.u64 %0, t; }" : "=r"(a) : "l"(p));
    return a;
}

__device__ __forceinline__ void ldsm4(unsigned* r, uint32_t a) {
    asm volatile("ldmatrix.sync.aligned.m8n8.x4.shared.b16 {%0,%1,%2,%3}, [%4];"
                 : "=r"(r[0]), "=r"(r[1]), "=r"(r[2]), "=r"(r[3]) : "r"(a));
}

// ---------------- pack pass: fp32 -> fp16 pair plane ----------------
__global__ void pack16_kernel(const float* __restrict__ X,
                              unsigned* __restrict__ O, int npairs)
{
    int i = blockIdx.x * blockDim.x + threadIdx.x;
    if (i >= npairs) return;
    float2 v = ((const float2*)X)[i];
    O[i] = packh2(v.x, v.y);
}

// ---------------- transpose + split V -> bf16 planes [b,hk,d,s-pairs] ----------------
__global__ void __launch_bounds__(256) transpose_split_v(const float* __restrict__ V,
                                                         unsigned* __restrict__ Oh,
                                                         unsigned* __restrict__ Ol)
{
    __shared__ float sm[64 * 132];
    const int tid = threadIdx.x;
    const int s0  = blockIdx.x * 64;
    const int hk  = blockIdx.y;
    const int b   = blockIdx.z;

#pragma unroll
    for (int i = 0; i < 32; i++) {
        int idx = tid + i * 256;
        int r = idx >> 7, c = idx & 127;
        sm[r * 132 + c] = V[(size_t)(b * S_ + s0 + r) * KVD_ + hk * HD_ + c];
    }
    __syncthreads();

    const int d  = tid >> 1;
    const int pb = (tid & 1) * 16;
    unsigned* oh = Oh + ((size_t)(b * HK_ + hk) * HD_ + d) * SP_ + (s0 >> 1) + pb;
    unsigned* ol = Ol + ((size_t)(b * HK_ + hk) * HD_ + d) * SP_ + (s0 >> 1) + pb;
#pragma unroll
    for (int i = 0; i < 16; i++) {
        int p = pb + i;
        float f0 = sm[(2 * p) * 132 + d];
        float f1 = sm[(2 * p + 1) * 132 + d];
        unsigned hi, lo;
        split2(f0, f1, hi, lo);
        oh[i] = hi; ol[i] = lo;
    }
}

// =====================================================================
// fp16 single-stream GEMM (ldmatrix fragments):
// C[M,N] = A[M,K]*B[N,K]^T, CTA tile 256x128, BK=64, 512 threads,
// 16 warps of 64x32, 3-stage cp.async.
// MODE 0: fp32 C. MODE 1: rope+scale+bf16split Q. MODE 2: rope+split K.
// =====================================================================
#define GSTR 36                       // smem row stride (u32): 32 data + 4 pad
#define APLU (256 * GSTR)             // 9216 u32
#define BPLU (128 * GSTR)             // 4608 u32
#define GSTGU (APLU + BPLU)           // 13824 u32 per stage
#define G_SMEM (3 * GSTGU * 4)        // 165888 B

template <int MODE>
__global__ void __launch_bounds__(512, 1)
gemm16(const unsigned* __restrict__ Ap, const unsigned* __restrict__ Bp,
       float* __restrict__ C, unsigned* __restrict__ Oh, unsigned* __restrict__ Ol,
       const float* __restrict__ cs, const float* __restrict__ sn,
       int N, int K)
{
    extern __shared__ unsigned gs[];

    const int tid  = threadIdx.x;
    const int lane = tid & 31;
    const int warp = tid >> 5;
    const int m0 = blockIdx.y << 8;
    const int n0 = blockIdx.x << 7;
    const int wm = (warp >> 2) * 64;
    const int wn = (warp & 3) * 32;
    const int grp = lane >> 2;
    const int qid = lane & 3;
    const int KP = K >> 1;

    // cp.async mapping
    const int lra = tid >> 1;
    const int lca = (tid & 1) * 16;
    const int lrb = tid >> 2;
    const int lcb = (tid & 3) * 8;
    const unsigned* ag = Ap + (size_t)(m0 + lra) * KP + lca;
    const unsigned* bg = Bp + (size_t)(n0 + lrb) * KP + lcb;

    const unsigned sbase = s2u(gs);
    const unsigned sra = (lra * GSTR + lca) * 4;
    const unsigned srb = (lrb * GSTR + lcb) * 4;

    // ldmatrix lane offsets (bytes, within plane)
    const unsigned aoff = (unsigned)((wm + (lane & 15)) * GSTR * 4 + (lane >> 4) * 16);
    const unsigned boff = (unsigned)((wn + (lane >> 4) * 8 + (lane & 7)) * GSTR * 4
                                     + ((lane >> 3) & 1) * 16);

    float acc[4][4][4];
#pragma unroll
    for (int i = 0; i < 4; i++)
#pragma unroll
        for (int j = 0; j < 4; j++)
#pragma unroll
            for (int c = 0; c < 4; c++) acc[i][j][c] = 0.0f;

    const int nch = K / 64;

    auto issue = [&](int c, int stg) {
        unsigned sb = sbase + (unsigned)(stg * GSTGU * 4);
        const int go = c * 32;
        cpa16(sb + sra,                ag + go);
        cpa16(sb + sra + 16,           ag + go + 4);
        cpa16(sb + sra + 32,           ag + go + 8);
        cpa16(sb + sra + 48,           ag + go + 12);
        cpa16(sb + APLU * 4 + srb,       bg + go);
        cpa16(sb + APLU * 4 + srb + 16,  bg + go + 4);
        asm volatile("cp.async.commit_group;");
    };

    issue(0, 0);
    if (nch > 1) issue(1, 1);

    int stg = 0;
    for (int c = 0; c < nch; c++) {
        if (c + 2 < nch) issue(c + 2, (stg + 2) % 3);
        const int rem = nch - 1 - c;
        if (rem >= 2)      { asm volatile("cp.async.wait_group 2;"); }
        else if (rem == 1) { asm volatile("cp.async.wait_group 1;"); }
        else               { asm volatile("cp.async.wait_group 0;"); }
        __syncthreads();

        const unsigned sA = sbase + (unsigned)(stg * GSTGU * 4);
        const unsigned sB = sA + APLU * 4;

#pragma unroll
        for (int kk = 0; kk < 4; kk++) {
            unsigned af[4][4];
#pragma unroll
            for (int mi = 0; mi < 4; mi++)
                ldsm4(af[mi], sA + aoff + mi * (16 * GSTR * 4) + kk * 32);
#pragma unroll
            for (int njp = 0; njp < 2; njp++) {
                unsigned bf[4];
                ldsm4(bf, sB + boff + njp * (16 * GSTR * 4) + kk * 32);
#pragma unroll
                for (int mi = 0; mi < 4; mi++) {
                    mma_fp16(acc[mi][2 * njp],     af[mi], bf[0], bf[1]);
                    mma_fp16(acc[mi][2 * njp + 1], af[mi], bf[2], bf[3]);
                }
            }
        }
        __syncthreads();
        stg = (stg + 1) % 3;
    }

    // ---- epilogue ----
#pragma unroll
    for (int mi = 0; mi < 4; mi++) {
        int row0 = m0 + wm + mi * 16 + grp;
#pragma unroll
        for (int nj = 0; nj < 4; nj++) {
            int col = n0 + wn + nj * 8 + qid * 2;
            if (MODE == 0) {
                *(float2*)(C + (size_t)row0 * N + col) =
                    make_float2(acc[mi][nj][0], acc[mi][nj][1]);
                *(float2*)(C + (size_t)(row0 + 8) * N + col) =
                    make_float2(acc[mi][nj][2], acc[mi][nj][3]);
            } else {
                const int d2 = (col >> 1) & 63;
#pragma unroll
                for (int half = 0; half < 2; half++) {
                    int r = row0 + half * 8;
                    float x0 = acc[mi][nj][half * 2];
                    float x1 = acc[mi][nj][half * 2 + 1];
                    int s = r & (S_ - 1);
                    float cc = cs[s * 64 + d2];
                    float sv = sn[s * 64 + d2];
                    float o0 = x0 * cc - x1 * sv;
                    float o1 = x0 * sv + x1 * cc;
                    if (MODE == 1) {
                        const float scale = 0.08838834764831845f;
                        o0 *= scale; o1 *= scale;
                    }
                    unsigned hi, lo;
                    split2(o0, o1, hi, lo);
                    size_t o;
                    if (MODE == 1) o = (size_t)r * DP_ + (col >> 1);
                    else {
                        int b = r >> 11, ss = r & (S_ - 1), hk = col >> 7;
                        o = ((size_t)(b * HK_ + hk) * S_ + ss) * 64 + d2;
                    }
                    Oh[o] = hi; Ol[o] = lo;
                }
            }
        }
    }
}

// =====================================================================
// Flash attention, bf16x3 mma.sync + ldmatrix fragments, causal, GQA.
// =====================================================================
#define KSTR 68
#define VSTR 36
#define KPLU (64 * KSTR)
#define VPLU (128 * VSTR)
#define ASTGU (2 * KPLU + 2 * VPLU)
#define A_SMEM ((2 * ASTGU + 2 * VPLU) * 4)

__global__ void __launch_bounds__(256, 1) attn_mma(const unsigned* __restrict__ Qh,
                                                   const unsigned* __restrict__ Ql,
                                                   const unsigned* __restrict__ Kp,
                                                   const unsigned* __restrict__ Klp,
                                                   const unsigned* __restrict__ Vth,
                                                   const unsigned* __restrict__ Vtl,
                                                   unsigned* __restrict__ Of16)
{
    extern __shared__ unsigned smu[];
    const unsigned sm_base = s2u(smu);
    unsigned* Ph = smu + 2 * ASTGU;
    unsigned* Pl = Ph + VPLU;
    const unsigned phb = sm_base + (unsigned)(2 * ASTGU * 4);   // Ph bytes
    const unsigned plb = phb + (unsigned)(VPLU * 4);

    const int tid  = threadIdx.x;
    const int lane = tid & 31;
    const int warp = tid >> 5;
    const int grp  = lane >> 2;
    const int qid  = lane & 3;
    const int qt = blockIdx.x;
    const int h  = blockIdx.y;
    const int b  = blockIdx.z;
    const int hk = h >> 2;
    const int q0  = qt * 128;
    const int wq0 = warp * 16;

    const unsigned* kbh = Kp  + (size_t)(b * HK_ + hk) * S_ * 64;
    const unsigned* kbl = Klp + (size_t)(b * HK_ + hk) * S_ * 64;
    const unsigned* vbh = Vth + (size_t)(b * HK_ + hk) * HD_ * SP_;
    const unsigned* vbl = Vtl + (size_t)(b * HK_ + hk) * HD_ * SP_;

    // ldmatrix lane offsets (bytes)
    const unsigned koff = (unsigned)(((lane >> 4) * 8 + (lane & 7)) * KSTR * 4
                                     + ((lane >> 3) & 1) * 16);
    const unsigned voff = (unsigned)(((lane >> 4) * 8 + (lane & 7)) * VSTR * 4
                                     + ((lane >> 3) & 1) * 16);
    const unsigned poff = (unsigned)((wq0 + (lane & 15)) * VSTR * 4 + (lane >> 4) * 16);

    unsigned qh[8][4], ql[8][4];
    {
        const unsigned* q0h = Qh + (size_t)(b * S_ + q0 + wq0) * DP_ + h * 64;
        const unsigned* q0l = Ql + (size_t)(b * S_ + q0 + wq0) * DP_ + h * 64;
#pragma unroll
        for (int kk = 0; kk < 8; kk++) {
            qh[kk][0] = q0h[(size_t)grp * DP_ + kk * 8 + qid];
            qh[kk][1] = q0h[(size_t)(grp + 8) * DP_ + kk * 8 + qid];
            qh[kk][2] = q0h[(size_t)grp * DP_ + kk * 8 + qid + 4];
            qh[kk][3] = q0h[(size_t)(grp + 8) * DP_ + kk * 8 + qid + 4];
            ql[kk][0] = q0l[(size_t)grp * DP_ + kk * 8 + qid];
            ql[kk][1] = q0l[(size_t)(grp + 8) * DP_ + kk * 8 + qid];
            ql[kk][2] = q0l[(size_t)grp * DP_ + kk * 8 + qid + 4];
            ql[kk][3] = q0l[(size_t)(grp + 8) * DP_ + kk * 8 + qid + 4];
        }
    }

    float o_acc[16][4];
#pragma unroll
    for (int i = 0; i < 16; i++)
#pragma unroll
        for (int c = 0; c < 4; c++) o_acc[i][c] = 0.0f;
    float m0r = -1e30f, m1r = -1e30f, l0r = 0.0f, l1r = 0.0f;

    const int qrow0 = q0 + wq0 + grp;
    const int tmax = 2 * qt + 1;

    const int krr = tid >> 2;
    const int kcc = tid & 3;
    const int vrr = tid >> 1;
    const int vcc = tid & 1;

    auto issueT = [&](int tt, int stg) {
        const unsigned sb = sm_base + (unsigned)(stg * ASTGU * 4);
        const int kv = tt * 64;
        const unsigned* gkh = kbh + (size_t)(kv + krr) * 64 + kcc * 4;
        const unsigned* gkl = kbl + (size_t)(kv + krr) * 64 + kcc * 4;
        const unsigned ks = sb + krr * (KSTR * 4) + kcc * 16;
#pragma unroll
        for (int j = 0; j < 4; j++) {
            cpa16(ks + j * 64,            gkh + j * 16);
            cpa16(ks + KPLU * 4 + j * 64, gkl + j * 16);
        }
        const unsigned* gvh = vbh + (size_t)vrr * SP_ + (kv >> 1) + vcc * 4;
        const unsigned* gvl = vbl + (size_t)vrr * SP_ + (kv >> 1) + vcc * 4;
        const unsigned vs = sb + 2 * KPLU * 4 + vrr * (VSTR * 4) + vcc * 16;
#pragma unroll
        for (int j = 0; j < 4; j++) {
            cpa16(vs + j * 32,            gvh + j * 8);
            cpa16(vs + VPLU * 4 + j * 32, gvl + j * 8);
        }
        asm volatile("cp.async.commit_group;");
    };

    issueT(0, 0);

    for (int t = 0; t <= tmax; t++) {
        const int kv0 = t * 64;
        if (t < tmax) {
            issueT(t + 1, (t + 1) & 1);
            asm volatile("cp.async.wait_group 1;");
        } else {
            asm volatile("cp.async.wait_group 0;");
        }
        __syncthreads();

        if (kv0 <= q0 + wq0 + 15) {
            const unsigned skh = sm_base + (unsigned)((t & 1) * ASTGU * 4);
            const unsigned skl = skh + (unsigned)(KPLU * 4);
            const unsigned svh = skl + (unsigned)(KPLU * 4);
            const unsigned svl = svh + (unsigned)(VPLU * 4);

            // ---- S = Q K^T ----
            float s[8][4];
#pragma unroll
            for (int nj = 0; nj < 8; nj++)
#pragma unroll
                for (int c = 0; c < 4; c++) s[nj][c] = 0.0f;

#pragma unroll
            for (int kk = 0; kk < 8; kk++) {
#pragma unroll
                for (int njp = 0; njp < 4; njp++) {
                    unsigned fh[4], fl[4];
                    ldsm4(fh, skh + koff + njp * (16 * KSTR * 4) + kk * 32);
                    ldsm4(fl, skl + koff + njp * (16 * KSTR * 4) + kk * 32);
                    mma3(s[2 * njp],     qh[kk], ql[kk], fh[0], fh[1], fl[0], fl[1]);
                    mma3(s[2 * njp + 1], qh[kk], ql[kk], fh[2], fh[3], fl[2], fl[3]);
                }
            }

            if (kv0 + 63 > q0 + wq0) {
#pragma unroll
                for (int nj = 0; nj < 8; nj++) {
                    int kcol = kv0 + nj * 8 + 2 * qid;
                    if (kcol     > qrow0)     s[nj][0] = -1e30f;
                    if (kcol + 1 > qrow0)     s[nj][1] = -1e30f;
                    if (kcol     > qrow0 + 8) s[nj][2] = -1e30f;
                    if (kcol + 1 > qrow0 + 8) s[nj][3] = -1e30f;
                }
            }

            // ---- online softmax ----
            float rm0 = -1e30f, rm1 = -1e30f;
#pragma unroll
            for (int nj = 0; nj < 8; nj++) {
                rm0 = fmaxf(rm0, fmaxf(s[nj][0], s[nj][1]));
                rm1 = fmaxf(rm1, fmaxf(s[nj][2], s[nj][3]));
            }
            rm0 = fmaxf(rm0, __shfl_xor_sync(0xffffffffu, rm0, 1));
            rm0 = fmaxf(rm0, __shfl_xor_sync(0xffffffffu, rm0, 2));
            rm1 = fmaxf(rm1, __shfl_xor_sync(0xffffffffu, rm1, 1));
            rm1 = fmaxf(rm1, __shfl_xor_sync(0xffffffffu, rm1, 2));

            float mn0 = fmaxf(m0r, rm0), mn1 = fmaxf(m1r, rm1);
            float a0 = __expf(m0r - mn0), a1 = __expf(m1r - mn1);
            m0r = mn0; m1r = mn1;

            float rs0 = 0.0f, rs1 = 0.0f;
#pragma unroll
            for (int nj = 0; nj < 8; nj++) {
                s[nj][0] = __expf(s[nj][0] - mn0);
                s[nj][1] = __expf(s[nj][1] - mn0);
                s[nj][2] = __expf(s[nj][2] - mn1);
                s[nj][3] = __expf(s[nj][3] - mn1);
                rs0 += s[nj][0] + s[nj][1];
                rs1 += s[nj][2] + s[nj][3];
            }
            rs0 += __shfl_xor_sync(0xffffffffu, rs0, 1);
            rs0 += __shfl_xor_sync(0xffffffffu, rs0, 2);
            rs1 += __shfl_xor_sync(0xffffffffu, rs1, 1);
            rs1 += __shfl_xor_sync(0xffffffffu, rs1, 2);
            l0r = l0r * a0 + rs0;
            l1r = l1r * a1 + rs1;

#pragma unroll
            for (int nj = 0; nj < 16; nj++) {
                o_acc[nj][0] *= a0; o_acc[nj][1] *= a0;
                o_acc[nj][2] *= a1; o_acc[nj][3] *= a1;
            }

            // ---- write P (exact hi/lo split), warp-private rows ----
#pragma unroll
            for (int nj = 0; nj < 8; nj++) {
                unsigned hi, lo;
                split2(s[nj][0], s[nj][1], hi, lo);
                Ph[(wq0 + grp) * VSTR + nj * 4 + qid] = hi;
                Pl[(wq0 + grp) * VSTR + nj * 4 + qid] = lo;
                split2(s[nj][2], s[nj][3], hi, lo);
                Ph[(wq0 + grp + 8) * VSTR + nj * 4 + qid] = hi;
                Pl[(wq0 + grp + 8) * VSTR + nj * 4 + qid] = lo;
            }
            __syncwarp();

            // ---- O += P V ----
#pragma unroll
            for (int kk = 0; kk < 4; kk++) {
                unsigned pah[4], pal[4];
                ldsm4(pah, phb + poff + kk * 32);
                ldsm4(pal, plb + poff + kk * 32);
#pragma unroll
                for (int njp = 0; njp < 8; njp++) {
                    unsigned fh[4], fl[4];
                    ldsm4(fh, svh + voff + njp * (16 * VSTR * 4) + kk * 32);
                    ldsm4(fl, svl + voff + njp * (16 * VSTR * 4) + kk * 32);
                    mma3(o_acc[2 * njp],     pah, pal, fh[0], fh[1], fl[0], fl[1]);
                    mma3(o_acc[2 * njp + 1], pah, pal, fh[2], fh[3], fl[2], fl[3]);
                }
            }
        }
        __syncthreads();
    }

    const float il0 = 1.0f / l0r;
    const float il1 = 1.0f / l1r;
    const size_t r0 = (size_t)(b * S_ + q0 + wq0 + grp) * DP_;
    const size_t r1 = (size_t)(b * S_ + q0 + wq0 + grp + 8) * DP_;
#pragma unroll
    for (int nj = 0; nj < 16; nj++) {
        int col = h * 64 + nj * 4 + qid;
        Of16[r0 + col] = packh2(o_acc[nj][0] * il0, o_acc[nj][1] * il0);
        Of16[r1 + col] = packh2(o_acc[nj][2] * il1, o_acc[nj][3] * il1);
    }
}

// =====================================================================
// launch
// =====================================================================
extern "C" void kernel_launch(void* const* d_in, const int* in_sizes, int n_in,
                              void* d_out, int out_size)
{
    const float* x  = (const float*)d_in[0];
    const float* fc = (const float*)d_in[1];
    const float* fs = (const float*)d_in[2];
    const float* wq = (const float*)d_in[3];
    const float* wk = (const float*)d_in[4];
    const float* wv = (const float*)d_in[5];
    const float* wo = (const float*)d_in[6];
    float* out = (float*)d_out;

    float *v;
    unsigned *x16, *wq16, *wk16, *wv16, *wo16, *af16;
    unsigned *qh, *ql, *khp, *klp, *vth, *vtl;
    cudaGetSymbolAddress((void**)&v,    g_v);
    cudaGetSymbolAddress((void**)&x16,  g_x16);
    cudaGetSymbolAddress((void**)&wq16, g_wq16);
    cudaGetSymbolAddress((void**)&wk16, g_wk16);
    cudaGetSymbolAddress((void**)&wv16, g_wv16);
    cudaGetSymbolAddress((void**)&wo16, g_wo16);
    cudaGetSymbolAddress((void**)&af16, g_af16);
    cudaGetSymbolAddress((void**)&qh,  g_qh);  cudaGetSymbolAddress((void**)&ql,  g_ql);
    cudaGetSymbolAddress((void**)&khp, g_khp); cudaGetSymbolAddress((void**)&klp, g_klp);
    cudaGetSymbolAddress((void**)&vth, g_vth); cudaGetSymbolAddress((void**)&vtl, g_vtl);

    // fp16 packs
    {
        int np;
        np = M_ * DP_;   pack16_kernel<<<np / 256, 256>>>(x,  x16,  np);
        np = D_ * DP_;   pack16_kernel<<<np / 256, 256>>>(wq, wq16, np);
        np = KVD_ * DP_; pack16_kernel<<<np / 256, 256>>>(wk, wk16, np);
        np = KVD_ * DP_; pack16_kernel<<<np / 256, 256>>>(wv, wv16, np);
        np = D_ * DP_;   pack16_kernel<<<np / 256, 256>>>(wo, wo16, np);
    }

    cudaFuncSetAttribute(gemm16<0>, cudaFuncAttributeMaxDynamicSharedMemorySize, G_SMEM);
    cudaFuncSetAttribute(gemm16<1>, cudaFuncAttributeMaxDynamicSharedMemorySize, G_SMEM);
    cudaFuncSetAttribute(gemm16<2>, cudaFuncAttributeMaxDynamicSharedMemorySize, G_SMEM);

    // projections (fp16 single-stream; Q,K with fused rope+bf16split epilogue)
    gemm16<1><<<dim3(32, 16), 512, G_SMEM>>>(x16, wq16, nullptr, qh, ql, fc, fs, D_, D_);
    gemm16<2><<<dim3(8,  16), 512, G_SMEM>>>(x16, wk16, nullptr, khp, klp, fc, fs, KVD_, D_);
    gemm16<0><<<dim3(8,  16), 512, G_SMEM>>>(x16, wv16, v, nullptr, nullptr, nullptr, nullptr, KVD_, D_);

    // V transpose+split (bf16 planes)
    transpose_split_v<<<dim3(S_ / 64, HK_, B_), 256>>>(v, vth, vtl);

    // attention (bf16x3 core + ldmatrix, fp16 output plane)
    cudaFuncSetAttribute(attn_mma, cudaFuncAttributeMaxDynamicSharedMemorySize, A_SMEM);
    attn_mma<<<dim3(S_ / 128, H_, B_), 256, A_SMEM>>>(qh, ql, khp, klp, vth, vtl, af16);

    // output projection (fp16 single-stream)
    gemm16<0><<<dim3(32, 16), 512, G_SMEM>>>(af16, wo16, out, nullptr, nullptr, nullptr, nullptr, D_, D_);
}

// round 10
// speedup vs baseline: 2.2096x; 1.0005x over previous
#include <cuda_runtime.h>
#include <cuda_bf16.h>
#include <cuda_fp16.h>
#include <cstdint>
#include <math.h>

#define B_   2
#define S_   2048
#define D_   4096
#define H_   32
#define HK_  8
#define HD_  128
#define M_   (B_ * S_)          // 4096 total tokens
#define KVD_ (HK_ * HD_)        // 1024
#define DP_  (D_ / 2)           // 2048 u32 pairs per row
#define SP_  (S_ / 2)           // 1024 seq pairs

// ---------------- scratch (device globals; no allocation allowed) ----------------
__device__ float    g_v[(size_t)M_ * KVD_];
// fp16 packed pair planes (operands for projections)
__device__ unsigned g_x16[(size_t)M_ * DP_];
__device__ unsigned g_wq16[(size_t)D_ * DP_];
__device__ unsigned g_wk16[(size_t)KVD_ * DP_];
__device__ unsigned g_wv16[(size_t)KVD_ * DP_];
__device__ unsigned g_wo16[(size_t)D_ * DP_];
__device__ unsigned g_af16[(size_t)M_ * DP_];   // attention out (fp16 pairs)
// attention operand planes (bf16 hi/lo)
__device__ unsigned g_qh[(size_t)M_ * DP_],   g_ql[(size_t)M_ * DP_];
__device__ unsigned g_khp[(size_t)B_ * HK_ * S_ * 64], g_klp[(size_t)B_ * HK_ * S_ * 64];
__device__ unsigned g_vth[(size_t)B_ * HK_ * HD_ * SP_], g_vtl[(size_t)B_ * HK_ * HD_ * SP_];

// ---------------- helpers ----------------
__device__ __forceinline__ void split2(float x, float y, unsigned& hi, unsigned& lo) {
    __nv_bfloat16 xh = __float2bfloat16_rn(x);
    __nv_bfloat16 yh = __float2bfloat16_rn(y);
    __nv_bfloat16 xl = __float2bfloat16_rn(x - __bfloat162float(xh));
    __nv_bfloat16 yl = __float2bfloat16_rn(y - __bfloat162float(yh));
    hi = (unsigned)__bfloat16_as_ushort(xh) | ((unsigned)__bfloat16_as_ushort(yh) << 16);
    lo = (unsigned)__bfloat16_as_ushort(xl) | ((unsigned)__bfloat16_as_ushort(yl) << 16);
}

__device__ __forceinline__ unsigned packh2(float x, float y) {
    __half2 h = __floats2half2_rn(x, y);
    return *reinterpret_cast<unsigned*>(&h);
}

__device__ __forceinline__ void mma_bf16(float* c, const unsigned* a, unsigned b0, unsigned b1) {
    asm volatile(
        "mma.sync.aligned.m16n8k16.row.col.f32.bf16.bf16.f32 "
        "{%0,%1,%2,%3}, {%4,%5,%6,%7}, {%8,%9}, {%0,%1,%2,%3};\n"
        : "+f"(c[0]), "+f"(c[1]), "+f"(c[2]), "+f"(c[3])
        : "r"(a[0]), "r"(a[1]), "r"(a[2]), "r"(a[3]), "r"(b0), "r"(b1));
}

__device__ __forceinline__ void mma_fp16(float* c, const unsigned* a, unsigned b0, unsigned b1) {
    asm volatile(
        "mma.sync.aligned.m16n8k16.row.col.f32.f16.f16.f32 "
        "{%0,%1,%2,%3}, {%4,%5,%6,%7}, {%8,%9}, {%0,%1,%2,%3};\n"
        : "+f"(c[0]), "+f"(c[1]), "+f"(c[2]), "+f"(c[3])
        : "r"(a[0]), "r"(a[1]), "r"(a[2]), "r"(a[3]), "r"(b0), "r"(b1));
}

__device__ __forceinline__ void mma3(float* c, const unsigned* ah, const unsigned* al,
                                     unsigned b0h, unsigned b1h, unsigned b0l, unsigned b1l) {
    mma_bf16(c, ah, b0h, b1h);
    mma_bf16(c, ah, b0l, b1l);
    mma_bf16(c, al, b0h, b1h);
}

__device__ __forceinline__ void cpa16(unsigned saddr, const void* g) {
    asm volatile("cp.async.cg.shared.global [%0], [%1], 16;" :: "r"(saddr), "l"(g));
}

__device__ __forceinline__ uint32_t s2u(const void* p) {
    uint32_t a;
    asm("{ .reg .u64 t; cvta.to.shared.u64 t, %1; cvt.u32.u64 %0, t; }" : "=r"(a) : "l"(p));
    return a;
}

__device__ __forceinline__ void ldsm4(unsigned* r, uint32_t a) {
    asm volatile("ldmatrix.sync.aligned.m8n8.x4.shared.b16 {%0,%1,%2,%3}, [%4];"
                 : "=r"(r[0]), "=r"(r[1]), "=r"(r[2]), "=r"(r[3]) : "r"(a));
}

// ---------------- pack pass: fp32 -> fp16 pair plane ----------------
__global__ void pack16_kernel(const float* __restrict__ X,
                              unsigned* __restrict__ O, int npairs)
{
    int i = blockIdx.x * blockDim.x + threadIdx.x;
    if (i >= npairs) return;
    float2 v = ((const float2*)X)[i];
    O[i] = packh2(v.x, v.y);
}

// ---------------- transpose + split V -> bf16 planes [b,hk,d,s-pairs] ----------------
__global__ void __launch_bounds__(256) transpose_split_v(const float* __restrict__ V,
                                                         unsigned* __restrict__ Oh,
                                                         unsigned* __restrict__ Ol)
{
    __shared__ float sm[64 * 132];
    const int tid = threadIdx.x;
    const int s0  = blockIdx.x * 64;
    const int hk  = blockIdx.y;
    const int b   = blockIdx.z;

#pragma unroll
    for (int i = 0; i < 32; i++) {
        int idx = tid + i * 256;
        int r = idx >> 7, c = idx & 127;
        sm[r * 132 + c] = V[(size_t)(b * S_ + s0 + r) * KVD_ + hk * HD_ + c];
    }
    __syncthreads();

    const int d  = tid >> 1;
    const int pb = (tid & 1) * 16;
    unsigned* oh = Oh + ((size_t)(b * HK_ + hk) * HD_ + d) * SP_ + (s0 >> 1) + pb;
    unsigned* ol = Ol + ((size_t)(b * HK_ + hk) * HD_ + d) * SP_ + (s0 >> 1) + pb;
#pragma unroll
    for (int i = 0; i < 16; i++) {
        int p = pb + i;
        float f0 = sm[(2 * p) * 132 + d];
        float f1 = sm[(2 * p + 1) * 132 + d];
        unsigned hi, lo;
        split2(f0, f1, hi, lo);
        oh[i] = hi; ol[i] = lo;
    }
}

// =====================================================================
// fp16 single-stream GEMM (ldmatrix fragments):
// C[M,N] = A[M,K]*B[N,K]^T, CTA tile 256x128, BK=64, 512 threads,
// 16 warps of 64x32, 3-stage cp.async.
// MODE 0: fp32 C. MODE 1: rope+scale+bf16split Q. MODE 2: rope+split K.
// =====================================================================
#define GSTR 36                       // smem row stride (u32): 32 data + 4 pad
#define APLU (256 * GSTR)             // 9216 u32
#define BPLU (128 * GSTR)             // 4608 u32
#define GSTGU (APLU + BPLU)           // 13824 u32 per stage
#define G_SMEM (3 * GSTGU * 4)        // 165888 B

template <int MODE>
__global__ void __launch_bounds__(512, 1)
gemm16(const unsigned* __restrict__ Ap, const unsigned* __restrict__ Bp,
       float* __restrict__ C, unsigned* __restrict__ Oh, unsigned* __restrict__ Ol,
       const float* __restrict__ cs, const float* __restrict__ sn,
       int N, int K)
{
    extern __shared__ unsigned gs[];

    const int tid  = threadIdx.x;
    const int lane = tid & 31;
    const int warp = tid >> 5;
    const int m0 = blockIdx.y << 8;
    const int n0 = blockIdx.x << 7;
    const int wm = (warp >> 2) * 64;
    const int wn = (warp & 3) * 32;
    const int grp = lane >> 2;
    const int qid = lane & 3;
    const int KP = K >> 1;

    // cp.async mapping
    const int lra = tid >> 1;
    const int lca = (tid & 1) * 16;
    const int lrb = tid >> 2;
    const int lcb = (tid & 3) * 8;
    const unsigned* ag = Ap + (size_t)(m0 + lra) * KP + lca;
    const unsigned* bg = Bp + (size_t)(n0 + lrb) * KP + lcb;

    const unsigned sbase = s2u(gs);
    const unsigned sra = (lra * GSTR + lca) * 4;
    const unsigned srb = (lrb * GSTR + lcb) * 4;

    // ldmatrix lane offsets (bytes, within plane)
    const unsigned aoff = (unsigned)((wm + (lane & 15)) * GSTR * 4 + (lane >> 4) * 16);
    const unsigned boff = (unsigned)((wn + (lane >> 4) * 8 + (lane & 7)) * GSTR * 4
                                     + ((lane >> 3) & 1) * 16);

    float acc[4][4][4];
#pragma unroll
    for (int i = 0; i < 4; i++)
#pragma unroll
        for (int j = 0; j < 4; j++)
#pragma unroll
            for (int c = 0; c < 4; c++) acc[i][j][c] = 0.0f;

    const int nch = K / 64;

    auto issue = [&](int c, int stg) {
        unsigned sb = sbase + (unsigned)(stg * GSTGU * 4);
        const int go = c * 32;
        cpa16(sb + sra,                ag + go);
        cpa16(sb + sra + 16,           ag + go + 4);
        cpa16(sb + sra + 32,           ag + go + 8);
        cpa16(sb + sra + 48,           ag + go + 12);
        cpa16(sb + APLU * 4 + srb,       bg + go);
        cpa16(sb + APLU * 4 + srb + 16,  bg + go + 4);
        asm volatile("cp.async.commit_group;");
    };

    issue(0, 0);
    if (nch > 1) issue(1, 1);

    int stg = 0;
    for (int c = 0; c < nch; c++) {
        if (c + 2 < nch) issue(c + 2, (stg + 2) % 3);
        const int rem = nch - 1 - c;
        if (rem >= 2)      { asm volatile("cp.async.wait_group 2;"); }
        else if (rem == 1) { asm volatile("cp.async.wait_group 1;"); }
        else               { asm volatile("cp.async.wait_group 0;"); }
        __syncthreads();

        const unsigned sA = sbase + (unsigned)(stg * GSTGU * 4);
        const unsigned sB = sA + APLU * 4;

#pragma unroll
        for (int kk = 0; kk < 4; kk++) {
            unsigned af[4][4];
#pragma unroll
            for (int mi = 0; mi < 4; mi++)
                ldsm4(af[mi], sA + aoff + mi * (16 * GSTR * 4) + kk * 32);
#pragma unroll
            for (int njp = 0; njp < 2; njp++) {
                unsigned bf[4];
                ldsm4(bf, sB + boff + njp * (16 * GSTR * 4) + kk * 32);
#pragma unroll
                for (int mi = 0; mi < 4; mi++) {
                    mma_fp16(acc[mi][2 * njp],     af[mi], bf[0], bf[1]);
                    mma_fp16(acc[mi][2 * njp + 1], af[mi], bf[2], bf[3]);
                }
            }
        }
        __syncthreads();
        stg = (stg + 1) % 3;
    }

    // ---- epilogue ----
#pragma unroll
    for (int mi = 0; mi < 4; mi++) {
        int row0 = m0 + wm + mi * 16 + grp;
#pragma unroll
        for (int nj = 0; nj < 4; nj++) {
            int col = n0 + wn + nj * 8 + qid * 2;
            if (MODE == 0) {
                *(float2*)(C + (size_t)row0 * N + col) =
                    make_float2(acc[mi][nj][0], acc[mi][nj][1]);
                *(float2*)(C + (size_t)(row0 + 8) * N + col) =
                    make_float2(acc[mi][nj][2], acc[mi][nj][3]);
            } else {
                const int d2 = (col >> 1) & 63;
#pragma unroll
                for (int half = 0; half < 2; half++) {
                    int r = row0 + half * 8;
                    float x0 = acc[mi][nj][half * 2];
                    float x1 = acc[mi][nj][half * 2 + 1];
                    int s = r & (S_ - 1);
                    float cc = cs[s * 64 + d2];
                    float sv = sn[s * 64 + d2];
                    float o0 = x0 * cc - x1 * sv;
                    float o1 = x0 * sv + x1 * cc;
                    if (MODE == 1) {
                        const float scale = 0.08838834764831845f;
                        o0 *= scale; o1 *= scale;
                    }
                    unsigned hi, lo;
                    split2(o0, o1, hi, lo);
                    size_t o;
                    if (MODE == 1) o = (size_t)r * DP_ + (col >> 1);
                    else {
                        int b = r >> 11, ss = r & (S_ - 1), hk = col >> 7;
                        o = ((size_t)(b * HK_ + hk) * S_ + ss) * 64 + d2;
                    }
                    Oh[o] = hi; Ol[o] = lo;
                }
            }
        }
    }
}

// =====================================================================
// Flash attention, bf16x3 mma.sync + ldmatrix fragments, causal, GQA.
// =====================================================================
#define KSTR 68
#define VSTR 36
#define KPLU (64 * KSTR)
#define VPLU (128 * VSTR)
#define ASTGU (2 * KPLU + 2 * VPLU)
#define A_SMEM ((2 * ASTGU + 2 * VPLU) * 4)

__global__ void __launch_bounds__(256, 1) attn_mma(const unsigned* __restrict__ Qh,
                                                   const unsigned* __restrict__ Ql,
                                                   const unsigned* __restrict__ Kp,
                                                   const unsigned* __restrict__ Klp,
                                                   const unsigned* __restrict__ Vth,
                                                   const unsigned* __restrict__ Vtl,
                                                   unsigned* __restrict__ Of16)
{
    extern __shared__ unsigned smu[];
    const unsigned sm_base = s2u(smu);
    unsigned* Ph = smu + 2 * ASTGU;
    unsigned* Pl = Ph + VPLU;
    const unsigned phb = sm_base + (unsigned)(2 * ASTGU * 4);   // Ph bytes
    const unsigned plb = phb + (unsigned)(VPLU * 4);

    const int tid  = threadIdx.x;
    const int lane = tid & 31;
    const int warp = tid >> 5;
    const int grp  = lane >> 2;
    const int qid  = lane & 3;
    const int qt = blockIdx.x;
    const int h  = blockIdx.y;
    const int b  = blockIdx.z;
    const int hk = h >> 2;
    const int q0  = qt * 128;
    const int wq0 = warp * 16;

    const unsigned* kbh = Kp  + (size_t)(b * HK_ + hk) * S_ * 64;
    const unsigned* kbl = Klp + (size_t)(b * HK_ + hk) * S_ * 64;
    const unsigned* vbh = Vth + (size_t)(b * HK_ + hk) * HD_ * SP_;
    const unsigned* vbl = Vtl + (size_t)(b * HK_ + hk) * HD_ * SP_;

    // ldmatrix lane offsets (bytes)
    const unsigned koff = (unsigned)(((lane >> 4) * 8 + (lane & 7)) * KSTR * 4
                                     + ((lane >> 3) & 1) * 16);
    const unsigned voff = (unsigned)(((lane >> 4) * 8 + (lane & 7)) * VSTR * 4
                                     + ((lane >> 3) & 1) * 16);
    const unsigned poff = (unsigned)((wq0 + (lane & 15)) * VSTR * 4 + (lane >> 4) * 16);

    unsigned qh[8][4], ql[8][4];
    {
        const unsigned* q0h = Qh + (size_t)(b * S_ + q0 + wq0) * DP_ + h * 64;
        const unsigned* q0l = Ql + (size_t)(b * S_ + q0 + wq0) * DP_ + h * 64;
#pragma unroll
        for (int kk = 0; kk < 8; kk++) {
            qh[kk][0] = q0h[(size_t)grp * DP_ + kk * 8 + qid];
            qh[kk][1] = q0h[(size_t)(grp + 8) * DP_ + kk * 8 + qid];
            qh[kk][2] = q0h[(size_t)grp * DP_ + kk * 8 + qid + 4];
            qh[kk][3] = q0h[(size_t)(grp + 8) * DP_ + kk * 8 + qid + 4];
            ql[kk][0] = q0l[(size_t)grp * DP_ + kk * 8 + qid];
            ql[kk][1] = q0l[(size_t)(grp + 8) * DP_ + kk * 8 + qid];
            ql[kk][2] = q0l[(size_t)grp * DP_ + kk * 8 + qid + 4];
            ql[kk][3] = q0l[(size_t)(grp + 8) * DP_ + kk * 8 + qid + 4];
        }
    }

    float o_acc[16][4];
#pragma unroll
    for (int i = 0; i < 16; i++)
#pragma unroll
        for (int c = 0; c < 4; c++) o_acc[i][c] = 0.0f;
    float m0r = -1e30f, m1r = -1e30f, l0r = 0.0f, l1r = 0.0f;

    const int qrow0 = q0 + wq0 + grp;
    const int tmax = 2 * qt + 1;

    const int krr = tid >> 2;
    const int kcc = tid & 3;
    const int vrr = tid >> 1;
    const int vcc = tid & 1;

    auto issueT = [&](int tt, int stg) {
        const unsigned sb = sm_base + (unsigned)(stg * ASTGU * 4);
        const int kv = tt * 64;
        const unsigned* gkh = kbh + (size_t)(kv + krr) * 64 + kcc * 4;
        const unsigned* gkl = kbl + (size_t)(kv + krr) * 64 + kcc * 4;
        const unsigned ks = sb + krr * (KSTR * 4) + kcc * 16;
#pragma unroll
        for (int j = 0; j < 4; j++) {
            cpa16(ks + j * 64,            gkh + j * 16);
            cpa16(ks + KPLU * 4 + j * 64, gkl + j * 16);
        }
        const unsigned* gvh = vbh + (size_t)vrr * SP_ + (kv >> 1) + vcc * 4;
        const unsigned* gvl = vbl + (size_t)vrr * SP_ + (kv >> 1) + vcc * 4;
        const unsigned vs = sb + 2 * KPLU * 4 + vrr * (VSTR * 4) + vcc * 16;
#pragma unroll
        for (int j = 0; j < 4; j++) {
            cpa16(vs + j * 32,            gvh + j * 8);
            cpa16(vs + VPLU * 4 + j * 32, gvl + j * 8);
        }
        asm volatile("cp.async.commit_group;");
    };

    issueT(0, 0);

    for (int t = 0; t <= tmax; t++) {
        const int kv0 = t * 64;
        if (t < tmax) {
            issueT(t + 1, (t + 1) & 1);
            asm volatile("cp.async.wait_group 1;");
        } else {
            asm volatile("cp.async.wait_group 0;");
        }
        __syncthreads();

        if (kv0 <= q0 + wq0 + 15) {
            const unsigned skh = sm_base + (unsigned)((t & 1) * ASTGU * 4);
            const unsigned skl = skh + (unsigned)(KPLU * 4);
            const unsigned svh = skl + (unsigned)(KPLU * 4);
            const unsigned svl = svh + (unsigned)(VPLU * 4);

            // ---- S = Q K^T ----
            float s[8][4];
#pragma unroll
            for (int nj = 0; nj < 8; nj++)
#pragma unroll
                for (int c = 0; c < 4; c++) s[nj][c] = 0.0f;

#pragma unroll
            for (int kk = 0; kk < 8; kk++) {
#pragma unroll
                for (int njp = 0; njp < 4; njp++) {
                    unsigned fh[4], fl[4];
                    ldsm4(fh, skh + koff + njp * (16 * KSTR * 4) + kk * 32);
                    ldsm4(fl, skl + koff + njp * (16 * KSTR * 4) + kk * 32);
                    mma3(s[2 * njp],     qh[kk], ql[kk], fh[0], fh[1], fl[0], fl[1]);
                    mma3(s[2 * njp + 1], qh[kk], ql[kk], fh[2], fh[3], fl[2], fl[3]);
                }
            }

            if (kv0 + 63 > q0 + wq0) {
#pragma unroll
                for (int nj = 0; nj < 8; nj++) {
                    int kcol = kv0 + nj * 8 + 2 * qid;
                    if (kcol     > qrow0)     s[nj][0] = -1e30f;
                    if (kcol + 1 > qrow0)     s[nj][1] = -1e30f;
                    if (kcol     > qrow0 + 8) s[nj][2] = -1e30f;
                    if (kcol + 1 > qrow0 + 8) s[nj][3] = -1e30f;
                }
            }

            // ---- online softmax ----
            float rm0 = -1e30f, rm1 = -1e30f;
#pragma unroll
            for (int nj = 0; nj < 8; nj++) {
                rm0 = fmaxf(rm0, fmaxf(s[nj][0], s[nj][1]));
                rm1 = fmaxf(rm1, fmaxf(s[nj][2], s[nj][3]));
            }
            rm0 = fmaxf(rm0, __shfl_xor_sync(0xffffffffu, rm0, 1));
            rm0 = fmaxf(rm0, __shfl_xor_sync(0xffffffffu, rm0, 2));
            rm1 = fmaxf(rm1, __shfl_xor_sync(0xffffffffu, rm1, 1));
            rm1 = fmaxf(rm1, __shfl_xor_sync(0xffffffffu, rm1, 2));

            float mn0 = fmaxf(m0r, rm0), mn1 = fmaxf(m1r, rm1);
            float a0 = __expf(m0r - mn0), a1 = __expf(m1r - mn1);
            m0r = mn0; m1r = mn1;

            float rs0 = 0.0f, rs1 = 0.0f;
#pragma unroll
            for (int nj = 0; nj < 8; nj++) {
                s[nj][0] = __expf(s[nj][0] - mn0);
                s[nj][1] = __expf(s[nj][1] - mn0);
                s[nj][2] = __expf(s[nj][2] - mn1);
                s[nj][3] = __expf(s[nj][3] - mn1);
                rs0 += s[nj][0] + s[nj][1];
                rs1 += s[nj][2] + s[nj][3];
            }
            rs0 += __shfl_xor_sync(0xffffffffu, rs0, 1);
            rs0 += __shfl_xor_sync(0xffffffffu, rs0, 2);
            rs1 += __shfl_xor_sync(0xffffffffu, rs1, 1);
            rs1 += __shfl_xor_sync(0xffffffffu, rs1, 2);
            l0r = l0r * a0 + rs0;
            l1r = l1r * a1 + rs1;

#pragma unroll
            for (int nj = 0; nj < 16; nj++) {
                o_acc[nj][0] *= a0; o_acc[nj][1] *= a0;
                o_acc[nj][2] *= a1; o_acc[nj][3] *= a1;
            }

            // ---- write P (exact hi/lo split), warp-private rows ----
#pragma unroll
            for (int nj = 0; nj < 8; nj++) {
                unsigned hi, lo;
                split2(s[nj][0], s[nj][1], hi, lo);
                Ph[(wq0 + grp) * VSTR + nj * 4 + qid] = hi;
                Pl[(wq0 + grp) * VSTR + nj * 4 + qid] = lo;
                split2(s[nj][2], s[nj][3], hi, lo);
                Ph[(wq0 + grp + 8) * VSTR + nj * 4 + qid] = hi;
                Pl[(wq0 + grp + 8) * VSTR + nj * 4 + qid] = lo;
            }
            __syncwarp();

            // ---- O += P V ----
#pragma unroll
            for (int kk = 0; kk < 4; kk++) {
                unsigned pah[4], pal[4];
                ldsm4(pah, phb + poff + kk * 32);
                ldsm4(pal, plb + poff + kk * 32);
#pragma unroll
                for (int njp = 0; njp < 8; njp++) {
                    unsigned fh[4], fl[4];
                    ldsm4(fh, svh + voff + njp * (16 * VSTR * 4) + kk * 32);
                    ldsm4(fl, svl + voff + njp * (16 * VSTR * 4) + kk * 32);
                    mma3(o_acc[2 * njp],     pah, pal, fh[0], fh[1], fl[0], fl[1]);
                    mma3(o_acc[2 * njp + 1], pah, pal, fh[2], fh[3], fl[2], fl[3]);
                }
            }
        }
        __syncthreads();
    }

    const float il0 = 1.0f / l0r;
    const float il1 = 1.0f / l1r;
    const size_t r0 = (size_t)(b * S_ + q0 + wq0 + grp) * DP_;
    const size_t r1 = (size_t)(b * S_ + q0 + wq0 + grp + 8) * DP_;
#pragma unroll
    for (int nj = 0; nj < 16; nj++) {
        int col = h * 64 + nj * 4 + qid;
        Of16[r0 + col] = packh2(o_acc[nj][0] * il0, o_acc[nj][1] * il0);
        Of16[r1 + col] = packh2(o_acc[nj][2] * il1, o_acc[nj][3] * il1);
    }
}

// =====================================================================
// launch
// =====================================================================
extern "C" void kernel_launch(void* const* d_in, const int* in_sizes, int n_in,
                              void* d_out, int out_size)
{
    const float* x  = (const float*)d_in[0];
    const float* fc = (const float*)d_in[1];
    const float* fs = (const float*)d_in[2];
    const float* wq = (const float*)d_in[3];
    const float* wk = (const float*)d_in[4];
    const float* wv = (const float*)d_in[5];
    const float* wo = (const float*)d_in[6];
    float* out = (float*)d_out;

    float *v;
    unsigned *x16, *wq16, *wk16, *wv16, *wo16, *af16;
    unsigned *qh, *ql, *khp, *klp, *vth, *vtl;
    cudaGetSymbolAddress((void**)&v,    g_v);
    cudaGetSymbolAddress((void**)&x16,  g_x16);
    cudaGetSymbolAddress((void**)&wq16, g_wq16);
    cudaGetSymbolAddress((void**)&wk16, g_wk16);
    cudaGetSymbolAddress((void**)&wv16, g_wv16);
    cudaGetSymbolAddress((void**)&wo16, g_wo16);
    cudaGetSymbolAddress((void**)&af16, g_af16);
    cudaGetSymbolAddress((void**)&qh,  g_qh);  cudaGetSymbolAddress((void**)&ql,  g_ql);
    cudaGetSymbolAddress((void**)&khp, g_khp); cudaGetSymbolAddress((void**)&klp, g_klp);
    cudaGetSymbolAddress((void**)&vth, g_vth); cudaGetSymbolAddress((void**)&vtl, g_vtl);

    // fp16 packs
    {
        int np;
        np = M_ * DP_;   pack16_kernel<<<np / 256, 256>>>(x,  x16,  np);
        np = D_ * DP_;   pack16_kernel<<<np / 256, 256>>>(wq, wq16, np);
        np = KVD_ * DP_; pack16_kernel<<<np / 256, 256>>>(wk, wk16, np);
        np = KVD_ * DP_; pack16_kernel<<<np / 256, 256>>>(wv, wv16, np);
        np = D_ * DP_;   pack16_kernel<<<np / 256, 256>>>(wo, wo16, np);
    }

    cudaFuncSetAttribute(gemm16<0>, cudaFuncAttributeMaxDynamicSharedMemorySize, G_SMEM);
    cudaFuncSetAttribute(gemm16<1>, cudaFuncAttributeMaxDynamicSharedMemorySize, G_SMEM);
    cudaFuncSetAttribute(gemm16<2>, cudaFuncAttributeMaxDynamicSharedMemorySize, G_SMEM);

    // projections (fp16 single-stream; Q,K with fused rope+bf16split epilogue)
    gemm16<1><<<dim3(32, 16), 512, G_SMEM>>>(x16, wq16, nullptr, qh, ql, fc, fs, D_, D_);
    gemm16<2><<<dim3(8,  16), 512, G_SMEM>>>(x16, wk16, nullptr, khp, klp, fc, fs, KVD_, D_);
    gemm16<0><<<dim3(8,  16), 512, G_SMEM>>>(x16, wv16, v, nullptr, nullptr, nullptr, nullptr, KVD_, D_);

    // V transpose+split (bf16 planes)
    transpose_split_v<<<dim3(S_ / 64, HK_, B_), 256>>>(v, vth, vtl);

    // attention (bf16x3 core + ldmatrix, fp16 output plane)
    cudaFuncSetAttribute(attn_mma, cudaFuncAttributeMaxDynamicSharedMemorySize, A_SMEM);
    attn_mma<<<dim3(S_ / 128, H_, B_), 256, A_SMEM>>>(qh, ql, khp, klp, vth, vtl, af16);

    // output projection (fp16 single-stream)
    gemm16<0><<<dim3(32, 16), 512, G_SMEM>>>(af16, wo16, out, nullptr, nullptr, nullptr, nullptr, D_, D_);
}